// round 7
// baseline (speedup 1.0000x reference)
#include <cuda_runtime.h>
#include <cstdint>
#include <cstddef>

// ---------------- problem constants ----------------
constexpr int Bb   = 8;
constexpr int Ll   = 128;
constexpr int Dd   = 768;
constexpr int DEP  = 64;
constexpr int POSN = 64;
constexpr int OUTN = 768;
constexpr int BI   = Bb * Ll;                       // 1024 (b,i) rows
constexpr long long R_SIZE = (long long)BI * Ll * OUTN;   // 100663296
constexpr long long OS_OFF = R_SIZE;                       // output_sum offset
constexpr long long P_OFF  = R_SIZE + (long long)BI * OUTN; // p offset
#define NEGC (-1e30f)

// ---------------- scratch (device globals; no allocs) ----------------
__device__ __align__(16) float g_A[BI * OUTN];     // A[b,i,o] = text@Wt + pos@Wp_attn + b_attn
__device__ __align__(16) float g_pd[BI * DEP];     // sum_j p * dep
__device__ float g_wt_sum[Dd];
__device__ float g_wp_sum[POSN];
__device__ float g_wd_sum[DEP];
__device__ float g_bias_out[OUTN];                 // bp + bd
__device__ float g_bsum;                           // sum(b_attn)

// ---------------- helpers ----------------
__device__ __forceinline__ float to_tf32(float x) {
    uint32_t u;
    asm("cvt.rna.tf32.f32 %0, %1;" : "=r"(u) : "f"(x));
    return __uint_as_float(u);
}
__device__ __forceinline__ void mma8(float c[4], const uint32_t a[4], const uint32_t b[2]) {
    asm volatile(
        "mma.sync.aligned.m16n8k8.row.col.f32.tf32.tf32.f32 "
        "{%0,%1,%2,%3},{%4,%5,%6,%7},{%8,%9},{%0,%1,%2,%3};\n"
        : "+f"(c[0]), "+f"(c[1]), "+f"(c[2]), "+f"(c[3])
        : "r"(a[0]), "r"(a[1]), "r"(a[2]), "r"(a[3]), "r"(b[0]), "r"(b[1]));
}
// k-permutation: pairs (t, t+4) become adjacent -> LDS.64 fragment loads
__device__ __forceinline__ int kperm(int k) {
    return (k & ~7) + 2 * (k & 3) + ((k >> 2) & 1);
}

// ---------------- K0: row sums + combined bias (warp-per-row) ----------------
__global__ void k0_sums(const float* __restrict__ Wt, const float* __restrict__ Wpa,
                        const float* __restrict__ Wda, const float* __restrict__ b_attn,
                        const float* __restrict__ bd, const float* __restrict__ bp) {
    const int gw   = (blockIdx.x * blockDim.x + threadIdx.x) >> 5;
    const int lane = threadIdx.x & 31;
    if (gw <= 896) {
        const float* src;
        if (gw < 768)      src = Wt  + (size_t)gw * 768;
        else if (gw < 832) src = Wpa + (size_t)(gw - 768) * 768;
        else if (gw < 896) src = Wda + (size_t)(gw - 832) * 768;
        else               src = b_attn;
        const float4* p4 = (const float4*)src;
        float s = 0.f;
        #pragma unroll
        for (int i = 0; i < 6; i++) { float4 v = p4[lane + i * 32]; s += v.x + v.y + v.z + v.w; }
        #pragma unroll
        for (int o = 16; o; o >>= 1) s += __shfl_xor_sync(0xffffffffu, s, o);
        if (lane == 0) {
            if (gw < 768)      g_wt_sum[gw] = s;
            else if (gw < 832) g_wp_sum[gw - 768] = s;
            else if (gw < 896) g_wd_sum[gw - 832] = s;
            else               g_bsum = s;
        }
    } else if (gw >= 897 && gw < 921) {
        int n = (gw - 897) * 32 + lane;
        g_bias_out[n] = bp[n] + bd[n];
    }
}

// ---------------- gemm_small: C[1024,768] = A1@B1 + A2@B2 + bias (+ addend) ----------------
// tf32 tensor-core GEMM. BM=32, BN=128, BK=32, 4 warps (warp tile 16x64). grid (6,32)=192 CTAs.
__global__ void __launch_bounds__(128) gemm_small(
    const float* __restrict__ A1, int lda1, const float* __restrict__ B1, int K1,
    const float* __restrict__ A2_, int lda2, const float* __restrict__ B2, int K2,
    int use_pd, const float* __restrict__ bias_, const float* __restrict__ addend,
    float* __restrict__ out_) {

    __shared__ float a_sm[32 * 36];
    __shared__ float b_sm[32 * 136];
    __shared__ float bias_s[128];

    const int tid   = threadIdx.x;
    const int nbase = blockIdx.x * 128;
    const int mbase = blockIdx.y * 32;
    const float* A2   = use_pd ? g_pd : A2_;
    float*       out  = out_ ? out_ : g_A;
    const float* bias = bias_ ? bias_ : g_bias_out;

    bias_s[tid] = bias[nbase + tid];

    const int w  = tid >> 5, lane = tid & 31;
    const int g  = lane >> 2, t = lane & 3;
    const int wm = w >> 1, wn = w & 1;

    float acc[8][4];
    #pragma unroll
    for (int nf = 0; nf < 8; nf++)
        #pragma unroll
        for (int q = 0; q < 4; q++) acc[nf][q] = 0.f;

    #pragma unroll
    for (int s = 0; s < 2; s++) {
        const float* Ap = s ? A2 : A1;
        const float* Bp = s ? B2 : B1;
        const int lda   = s ? lda2 : lda1;
        const int Ks    = s ? K2 : K1;
        for (int kt = 0; kt < Ks; kt += 32) {
            #pragma unroll
            for (int it = 0; it < 2; it++) {
                int idx = tid + it * 128;
                int row = idx >> 3, k4 = idx & 7;
                float4 v = *(const float4*)(Ap + (size_t)(mbase + row) * lda + kt + k4 * 4);
                float4 wv = make_float4(to_tf32(v.x), to_tf32(v.y), to_tf32(v.z), to_tf32(v.w));
                *(float4*)(a_sm + row * 36 + k4 * 4) = wv;
            }
            #pragma unroll
            for (int it = 0; it < 8; it++) {
                int idx = tid + it * 128;
                int kr = idx >> 5, c4 = idx & 31;
                float4 v = *(const float4*)(Bp + (size_t)(kt + kr) * 768 + nbase + c4 * 4);
                float4 wv = make_float4(to_tf32(v.x), to_tf32(v.y), to_tf32(v.z), to_tf32(v.w));
                *(float4*)(b_sm + kr * 136 + c4 * 4) = wv;
            }
            __syncthreads();
            #pragma unroll
            for (int ks = 0; ks < 4; ks++) {
                const int kb = ks * 8;
                uint32_t a[4], b[8][2];
                {
                    int r = wm * 16 + g;
                    a[0] = __float_as_uint(a_sm[r * 36 + kb + t]);
                    a[1] = __float_as_uint(a_sm[(r + 8) * 36 + kb + t]);
                    a[2] = __float_as_uint(a_sm[r * 36 + kb + 4 + t]);
                    a[3] = __float_as_uint(a_sm[(r + 8) * 36 + kb + 4 + t]);
                }
                #pragma unroll
                for (int nf = 0; nf < 8; nf++) {
                    int c = wn * 64 + nf * 8 + g;
                    b[nf][0] = __float_as_uint(b_sm[(kb + t) * 136 + c]);
                    b[nf][1] = __float_as_uint(b_sm[(kb + 4 + t) * 136 + c]);
                }
                #pragma unroll
                for (int nf = 0; nf < 8; nf++) mma8(acc[nf], a, b[nf]);
            }
            __syncthreads();
        }
    }

    #pragma unroll
    for (int nf = 0; nf < 8; nf++) {
        int r0 = mbase + wm * 16 + g;
        int cl = wn * 64 + nf * 8 + 2 * t;
        int c  = nbase + cl;
        float a0 = 0.f, a1 = 0.f, a2 = 0.f, a3 = 0.f;
        if (addend) {
            a0 = addend[(size_t)r0 * 768 + c];
            a1 = addend[(size_t)r0 * 768 + c + 1];
            a2 = addend[(size_t)(r0 + 8) * 768 + c];
            a3 = addend[(size_t)(r0 + 8) * 768 + c + 1];
        }
        float2 v0 = make_float2(acc[nf][0] + bias_s[cl] + a0, acc[nf][1] + bias_s[cl + 1] + a1);
        float2 v1 = make_float2(acc[nf][2] + bias_s[cl] + a2, acc[nf][3] + bias_s[cl + 1] + a3);
        *(float2*)(out + (size_t)r0 * 768 + c) = v0;
        *(float2*)(out + (size_t)(r0 + 8) * 768 + c) = v1;
    }
}

// ---------------- kernel S: scores + softmax + p + p-weighted dep ----------------
__global__ void __launch_bounds__(128) kernel_s(
    const float* __restrict__ text, const int* __restrict__ adj,
    const float* __restrict__ dep, const float* __restrict__ pos,
    float* __restrict__ p_out) {

    __shared__ float dep_s[128 * 65];
    __shared__ float ws_s[64];
    __shared__ float p_s[128];
    __shared__ float red[128];

    const int bi  = blockIdx.x;
    const int tid = threadIdx.x;
    const int lane = tid & 31;

    if (tid < 64) ws_s[tid] = g_wd_sum[tid];

    float ps = 0.f;
    #pragma unroll
    for (int d = tid; d < 768; d += 128) ps += text[(size_t)bi * 768 + d] * g_wt_sum[d];
    if (tid < 64) ps += pos[(size_t)bi * 64 + tid] * g_wp_sum[tid];
    #pragma unroll
    for (int o = 16; o; o >>= 1) ps += __shfl_xor_sync(0xffffffffu, ps, o);
    if (lane == 0) red[tid >> 5] = ps;
    __syncthreads();
    const float s_base = red[0] + red[1] + red[2] + red[3] + g_bsum;
    __syncthreads();

    const float4* dr = (const float4*)(dep + ((size_t)bi * 128 + tid) * 64);
    float dot = 0.f;
    #pragma unroll
    for (int q = 0; q < 16; q++) {
        float4 v = dr[q];
        dot += v.x * ws_s[4 * q] + v.y * ws_s[4 * q + 1] + v.z * ws_s[4 * q + 2] + v.w * ws_s[4 * q + 3];
        int base = tid * 65 + 4 * q;
        dep_s[base]     = v.x;
        dep_s[base + 1] = v.y;
        dep_s[base + 2] = v.z;
        dep_s[base + 3] = v.w;
    }
    const float score = s_base + dot + (adj[(size_t)bi * 128 + tid] == 0 ? NEGC : 0.f);

    float m = score;
    #pragma unroll
    for (int o = 16; o; o >>= 1) m = fmaxf(m, __shfl_xor_sync(0xffffffffu, m, o));
    if (lane == 0) red[tid >> 5] = m;
    __syncthreads();
    const float mx = fmaxf(fmaxf(red[0], red[1]), fmaxf(red[2], red[3]));
    __syncthreads();
    const float e = expf(score - mx);
    float z = e;
    #pragma unroll
    for (int o = 16; o; o >>= 1) z += __shfl_xor_sync(0xffffffffu, z, o);
    if (lane == 0) red[tid >> 5] = z;
    __syncthreads();
    const float Z = red[0] + red[1] + red[2] + red[3];
    const float p = e / Z;
    p_s[tid] = p;
    p_out[(size_t)bi * 128 + tid] = p;
    __syncthreads();

    const int half = tid >> 6, k = tid & 63;
    float s = 0.f;
    #pragma unroll 4
    for (int j = half * 64; j < half * 64 + 64; j++) s += p_s[j] * dep_s[j * 65 + k];
    red[tid] = s;
    __syncthreads();
    if (tid < 64) g_pd[(size_t)bi * 64 + tid] = red[tid] + red[tid + 64];
}

// ---------------- kernel R: r = dep @ Wd_attn + A  (persistent, 512 threads) ----------------
// grid (3, 49) = 147 CTAs (one wave). 16 warps (2 wm x 8 wn), warp tile 64x32.
// k-permuted layouts + stride 72 (== 8 mod 32) -> all fragment loads are
// conflict-free LDS.64. Wd stored column-major once per CTA; dep tile per bi
// with register prefetch. Epilogue = STG.128 streaming via column permutation.
constexpr int SD      = 72;                 // dep_s row stride
constexpr int SBC     = 72;                 // wd_s column stride
constexpr int R_DEPS  = 128 * SD;           // 9216 floats
constexpr int R_WDS   = 256 * SBC;          // 18432 floats
constexpr int R_SMEMB = (R_DEPS + R_WDS + 256) * 4;  // 111616 bytes
constexpr int NCH     = 49;

__global__ void __launch_bounds__(512, 1) kernel_r(
    const float* __restrict__ dep, const float* __restrict__ Wda,
    float* __restrict__ rout) {

    extern __shared__ float sm[];
    float* dep_s = sm;
    float* wd_s  = sm + R_DEPS;
    float* a_s   = sm + R_DEPS + R_WDS;

    const int tid = threadIdx.x;
    const int nt  = blockIdx.x;   // 0..2 N-tile of 256 cols

    // ---- Wd_attn slice [64 x 256] -> col-major, column-permuted, k-permuted (once) ----
    // actual col A = 16q+4T+d -> logical L = 16q + 8*(d>>1) + 2T + (d&1)
    #pragma unroll
    for (int it = 0; it < 8; it++) {
        int idx = tid + it * 512;
        int k = idx >> 6, c4 = idx & 63;
        float4 v = *(const float4*)(Wda + (size_t)k * 768 + nt * 256 + c4 * 4);
        int A  = c4 * 4;
        int L0 = (A & ~15) + (((A >> 2) & 3) << 1);
        int kp = kperm(k);
        wd_s[(size_t)L0 * SBC + kp]       = to_tf32(v.x);
        wd_s[(size_t)(L0 + 1) * SBC + kp] = to_tf32(v.y);
        wd_s[(size_t)(L0 + 8) * SBC + kp] = to_tf32(v.z);
        wd_s[(size_t)(L0 + 9) * SBC + kp] = to_tf32(v.w);
    }

    const int w  = tid >> 5, lane = tid & 31;
    const int g  = lane >> 2, t = lane & 3;
    const int wm = w >> 3, wn = w & 7;   // 2 x 8 warps; warp tile 64 x 32

    int bi = blockIdx.y;                 // strided by NCH

    // prefetch first dep tile (4 float4/thread) + A element
    float4 pf[4];
    float  pfa = 0.f;
    {
        const float4* db4 = (const float4*)(dep + (size_t)bi * 8192);
        #pragma unroll
        for (int it = 0; it < 4; it++) pf[it] = db4[tid + it * 512];
        if (tid < 256) pfa = g_A[(size_t)bi * 768 + nt * 256 + tid];
    }

    while (true) {
        __syncthreads();   // prior iteration's consumers done (iter0: wd_s init done)
        #pragma unroll
        for (int it = 0; it < 4; it++) {
            int idx = tid + it * 512;
            int j = idx >> 4, c = idx & 15;
            float* row = dep_s + j * SD;
            float4 v = pf[it];
            row[kperm(4 * c)]     = to_tf32(v.x);
            row[kperm(4 * c + 1)] = to_tf32(v.y);
            row[kperm(4 * c + 2)] = to_tf32(v.z);
            row[kperm(4 * c + 3)] = to_tf32(v.w);
        }
        if (tid < 256) a_s[tid] = pfa;
        __syncthreads();

        // prefetch next bi (hidden under mma + stores)
        const int bin = bi + NCH;
        if (bin < 1024) {
            const float4* db4 = (const float4*)(dep + (size_t)bin * 8192);
            #pragma unroll
            for (int it = 0; it < 4; it++) pf[it] = db4[tid + it * 512];
            if (tid < 256) pfa = g_A[(size_t)bin * 768 + nt * 256 + tid];
        }

        float acc[4][4][4];
        #pragma unroll
        for (int mf = 0; mf < 4; mf++)
            #pragma unroll
            for (int nf = 0; nf < 4; nf++)
                #pragma unroll
                for (int q = 0; q < 4; q++) acc[mf][nf][q] = 0.f;

        #pragma unroll
        for (int ks = 0; ks < 8; ks++) {
            const int kb = ks * 8;
            uint32_t a[4][4], b[4][2];
            #pragma unroll
            for (int mf = 0; mf < 4; mf++) {
                int r = wm * 64 + mf * 16 + g;
                float2 ar  = *(const float2*)(dep_s + r * SD + kb + 2 * t);
                float2 ar8 = *(const float2*)(dep_s + (r + 8) * SD + kb + 2 * t);
                a[mf][0] = __float_as_uint(ar.x);
                a[mf][1] = __float_as_uint(ar8.x);
                a[mf][2] = __float_as_uint(ar.y);
                a[mf][3] = __float_as_uint(ar8.y);
            }
            #pragma unroll
            for (int nf = 0; nf < 4; nf++) {
                int c = wn * 32 + nf * 8 + g;   // logical column
                float2 bv = *(const float2*)(wd_s + c * SBC + kb + 2 * t);
                b[nf][0] = __float_as_uint(bv.x);
                b[nf][1] = __float_as_uint(bv.y);
            }
            #pragma unroll
            for (int mf = 0; mf < 4; mf++)
                #pragma unroll
                for (int nf = 0; nf < 4; nf++) mma8(acc[mf][nf], a[mf], b[nf]);
        }

        // epilogue: +A, STG.128 streaming stores on actual (de-permuted) columns
        float* rbase = rout + (size_t)bi * 98304 + nt * 256;
        #pragma unroll
        for (int mf = 0; mf < 4; mf++) {
            #pragma unroll
            for (int q2 = 0; q2 < 2; q2++) {
                int r0  = wm * 64 + mf * 16 + g;
                int col = wn * 32 + (q2 << 4) + 4 * t;
                float4 a4 = *(float4*)(a_s + col);
                float4 w0 = make_float4(acc[mf][2 * q2][0] + a4.x, acc[mf][2 * q2][1] + a4.y,
                                        acc[mf][2 * q2 + 1][0] + a4.z, acc[mf][2 * q2 + 1][1] + a4.w);
                float4 w1 = make_float4(acc[mf][2 * q2][2] + a4.x, acc[mf][2 * q2][3] + a4.y,
                                        acc[mf][2 * q2 + 1][2] + a4.z, acc[mf][2 * q2 + 1][3] + a4.w);
                __stcs((float4*)(rbase + (size_t)r0 * 768 + col), w0);
                __stcs((float4*)(rbase + (size_t)(r0 + 8) * 768 + col), w1);
            }
        }

        bi = bin;
        if (bi >= 1024) break;
    }
}

// ---------------- launch ----------------
extern "C" void kernel_launch(void* const* d_in, const int* in_sizes, int n_in,
                              void* d_out, int out_size) {
    const float* text = (const float*)d_in[0];
    const int*   adj  = (const int*)d_in[1];
    const float* dep  = (const float*)d_in[2];
    const float* pos  = (const float*)d_in[3];
    const float* Wt   = (const float*)d_in[4];
    const float* Wpa  = (const float*)d_in[5];
    const float* Wda  = (const float*)d_in[6];
    const float* ba   = (const float*)d_in[7];
    const float* Wd   = (const float*)d_in[8];
    const float* bd   = (const float*)d_in[9];
    const float* Wp   = (const float*)d_in[10];
    const float* bp   = (const float*)d_in[11];
    float* out = (float*)d_out;

    cudaFuncSetAttribute(kernel_r, cudaFuncAttributeMaxDynamicSharedMemorySize, R_SMEMB);

    // 1) row sums + combined bias
    k0_sums<<<116, 256>>>(Wt, Wpa, Wda, ba, bd, bp);
    // 2) A = text@Wt + pos@Wp_attn + b_attn  -> g_A
    gemm_small<<<dim3(6, 32), 128>>>(text, 768, Wt, 768, pos, 64, Wpa, 64,
                                     /*use_pd=*/0, ba, nullptr, nullptr);
    // 3) scores/softmax -> p (out) and g_pd
    kernel_s<<<BI, 128>>>(text, adj, dep, pos, out + P_OFF);
    // 4) r = dep@Wd_attn + A  -> out[0 : R_SIZE)   (persistent, one wave, 512 thr)
    kernel_r<<<dim3(3, NCH), 512, R_SMEMB>>>(dep, Wda, out);
    // 5) output_sum = pos@Wp + g_pd@Wd + (bp+bd) + text -> out[OS_OFF : )
    gemm_small<<<dim3(6, 32), 128>>>(pos, 64, Wp, 64, nullptr, 64, Wd, 64,
                                     /*use_pd=*/1, nullptr, text, out + OS_OFF);
}

// round 8
// speedup vs baseline: 1.1750x; 1.1750x over previous
#include <cuda_runtime.h>
#include <cstdint>
#include <cstddef>

// ---------------- problem constants ----------------
constexpr int Bb   = 8;
constexpr int Ll   = 128;
constexpr int Dd   = 768;
constexpr int DEP  = 64;
constexpr int POSN = 64;
constexpr int OUTN = 768;
constexpr int BI   = Bb * Ll;                       // 1024 (b,i) rows
constexpr long long R_SIZE = (long long)BI * Ll * OUTN;   // 100663296
constexpr long long OS_OFF = R_SIZE;                       // output_sum offset
constexpr long long P_OFF  = R_SIZE + (long long)BI * OUTN; // p offset
#define NEGC (-1e30f)

// ---------------- scratch (device globals; no allocs) ----------------
__device__ __align__(16) float g_A[BI * OUTN];     // A[b,i,o]
__device__ __align__(16) float g_pd[BI * DEP];     // sum_j p * dep
__device__ __align__(16) float g_depc[(size_t)BI * 128 * 64]; // tf32-rounded dep (33.5 MB)
__device__ float g_wt_sum[Dd];
__device__ float g_wp_sum[POSN];
__device__ float g_wd_sum[DEP];
__device__ float g_bias_out[OUTN];                 // bp + bd
__device__ float g_bsum;                           // sum(b_attn)

// ---------------- helpers ----------------
__device__ __forceinline__ float to_tf32(float x) {
    uint32_t u;
    asm("cvt.rna.tf32.f32 %0, %1;" : "=r"(u) : "f"(x));
    return __uint_as_float(u);
}
__device__ __forceinline__ void mma8(float c[4], const uint32_t a[4], const uint32_t b[2]) {
    asm volatile(
        "mma.sync.aligned.m16n8k8.row.col.f32.tf32.tf32.f32 "
        "{%0,%1,%2,%3},{%4,%5,%6,%7},{%8,%9},{%0,%1,%2,%3};\n"
        : "+f"(c[0]), "+f"(c[1]), "+f"(c[2]), "+f"(c[3])
        : "r"(a[0]), "r"(a[1]), "r"(a[2]), "r"(a[3]), "r"(b[0]), "r"(b[1]));
}
__device__ __forceinline__ void cpasync16(uint32_t dst, const void* src) {
    asm volatile("cp.async.cg.shared.global [%0], [%1], 16;\n" :: "r"(dst), "l"(src));
}
__device__ __forceinline__ void cp_commit() {
    asm volatile("cp.async.commit_group;\n" ::: "memory");
}
template <int N>
__device__ __forceinline__ void cp_wait() {
    asm volatile("cp.async.wait_group %0;\n" :: "n"(N) : "memory");
}

// ---------------- K0: row sums + combined bias (warp-per-row) ----------------
__global__ void k0_sums(const float* __restrict__ Wt, const float* __restrict__ Wpa,
                        const float* __restrict__ Wda, const float* __restrict__ b_attn,
                        const float* __restrict__ bd, const float* __restrict__ bp) {
    const int gw   = (blockIdx.x * blockDim.x + threadIdx.x) >> 5;
    const int lane = threadIdx.x & 31;
    if (gw <= 896) {
        const float* src;
        if (gw < 768)      src = Wt  + (size_t)gw * 768;
        else if (gw < 832) src = Wpa + (size_t)(gw - 768) * 768;
        else if (gw < 896) src = Wda + (size_t)(gw - 832) * 768;
        else               src = b_attn;
        const float4* p4 = (const float4*)src;
        float s = 0.f;
        #pragma unroll
        for (int i = 0; i < 6; i++) { float4 v = p4[lane + i * 32]; s += v.x + v.y + v.z + v.w; }
        #pragma unroll
        for (int o = 16; o; o >>= 1) s += __shfl_xor_sync(0xffffffffu, s, o);
        if (lane == 0) {
            if (gw < 768)      g_wt_sum[gw] = s;
            else if (gw < 832) g_wp_sum[gw - 768] = s;
            else if (gw < 896) g_wd_sum[gw - 832] = s;
            else               g_bsum = s;
        }
    } else if (gw >= 897 && gw < 921) {
        int n = (gw - 897) * 32 + lane;
        g_bias_out[n] = bp[n] + bd[n];
    }
}

// ---------------- gemm_small (R6 version): BM=64, BN=128, BK=32, 4 warps ----------------
__global__ void __launch_bounds__(128) gemm_small(
    const float* __restrict__ A1, int lda1, const float* __restrict__ B1, int K1,
    const float* __restrict__ A2_, int lda2, const float* __restrict__ B2, int K2,
    int use_pd, const float* __restrict__ bias_, const float* __restrict__ addend,
    float* __restrict__ out_) {

    __shared__ float a_sm[64 * 36];
    __shared__ float b_sm[32 * 136];
    __shared__ float bias_s[128];

    const int tid   = threadIdx.x;
    const int nbase = blockIdx.x * 128;
    const int mbase = blockIdx.y * 64;
    const float* A2   = use_pd ? g_pd : A2_;
    float*       out  = out_ ? out_ : g_A;
    const float* bias = bias_ ? bias_ : g_bias_out;

    bias_s[tid] = bias[nbase + tid];

    const int w  = tid >> 5, lane = tid & 31;
    const int g  = lane >> 2, t = lane & 3;
    const int wm = w >> 1, wn = w & 1;

    float acc[2][8][4];
    #pragma unroll
    for (int mf = 0; mf < 2; mf++)
        #pragma unroll
        for (int nf = 0; nf < 8; nf++)
            #pragma unroll
            for (int q = 0; q < 4; q++) acc[mf][nf][q] = 0.f;

    #pragma unroll
    for (int s = 0; s < 2; s++) {
        const float* Ap = s ? A2 : A1;
        const float* Bp = s ? B2 : B1;
        const int lda   = s ? lda2 : lda1;
        const int Ks    = s ? K2 : K1;
        for (int kt = 0; kt < Ks; kt += 32) {
            #pragma unroll
            for (int it = 0; it < 4; it++) {
                int idx = tid + it * 128;
                int row = idx >> 3, k4 = idx & 7;
                float4 v = *(const float4*)(Ap + (size_t)(mbase + row) * lda + kt + k4 * 4);
                float4 wv = make_float4(to_tf32(v.x), to_tf32(v.y), to_tf32(v.z), to_tf32(v.w));
                *(float4*)(a_sm + row * 36 + k4 * 4) = wv;
            }
            #pragma unroll
            for (int it = 0; it < 8; it++) {
                int idx = tid + it * 128;
                int kr = idx >> 5, c4 = idx & 31;
                float4 v = *(const float4*)(Bp + (size_t)(kt + kr) * 768 + nbase + c4 * 4);
                float4 wv = make_float4(to_tf32(v.x), to_tf32(v.y), to_tf32(v.z), to_tf32(v.w));
                *(float4*)(b_sm + kr * 136 + c4 * 4) = wv;
            }
            __syncthreads();
            #pragma unroll
            for (int ks = 0; ks < 4; ks++) {
                const int kb = ks * 8;
                uint32_t a[2][4], b[8][2];
                #pragma unroll
                for (int mf = 0; mf < 2; mf++) {
                    int r = wm * 32 + mf * 16 + g;
                    a[mf][0] = __float_as_uint(a_sm[r * 36 + kb + t]);
                    a[mf][1] = __float_as_uint(a_sm[(r + 8) * 36 + kb + t]);
                    a[mf][2] = __float_as_uint(a_sm[r * 36 + kb + 4 + t]);
                    a[mf][3] = __float_as_uint(a_sm[(r + 8) * 36 + kb + 4 + t]);
                }
                #pragma unroll
                for (int nf = 0; nf < 8; nf++) {
                    int c = wn * 64 + nf * 8 + g;
                    b[nf][0] = __float_as_uint(b_sm[(kb + t) * 136 + c]);
                    b[nf][1] = __float_as_uint(b_sm[(kb + 4 + t) * 136 + c]);
                }
                #pragma unroll
                for (int mf = 0; mf < 2; mf++)
                    #pragma unroll
                    for (int nf = 0; nf < 8; nf++) mma8(acc[mf][nf], a[mf], b[nf]);
            }
            __syncthreads();
        }
    }

    #pragma unroll
    for (int mf = 0; mf < 2; mf++) {
        #pragma unroll
        for (int nf = 0; nf < 8; nf++) {
            int r0 = mbase + wm * 32 + mf * 16 + g;
            int cl = wn * 64 + nf * 8 + 2 * t;
            int c  = nbase + cl;
            float a0 = 0.f, a1 = 0.f, a2 = 0.f, a3 = 0.f;
            if (addend) {
                a0 = addend[(size_t)r0 * 768 + c];
                a1 = addend[(size_t)r0 * 768 + c + 1];
                a2 = addend[(size_t)(r0 + 8) * 768 + c];
                a3 = addend[(size_t)(r0 + 8) * 768 + c + 1];
            }
            float2 v0 = make_float2(acc[mf][nf][0] + bias_s[cl] + a0,
                                    acc[mf][nf][1] + bias_s[cl + 1] + a1);
            float2 v1 = make_float2(acc[mf][nf][2] + bias_s[cl] + a2,
                                    acc[mf][nf][3] + bias_s[cl + 1] + a3);
            *(float2*)(out + (size_t)r0 * 768 + c) = v0;
            *(float2*)(out + (size_t)(r0 + 8) * 768 + c) = v1;
        }
    }
}

// ---------------- kernel S: scores + softmax + p + p-weighted dep + tf32 dep copy ----------------
__global__ void __launch_bounds__(128) kernel_s(
    const float* __restrict__ text, const int* __restrict__ adj,
    const float* __restrict__ dep, const float* __restrict__ pos,
    float* __restrict__ p_out) {

    __shared__ float dep_s[128 * 65];
    __shared__ float ws_s[64];
    __shared__ float p_s[128];
    __shared__ float red[128];

    const int bi  = blockIdx.x;
    const int tid = threadIdx.x;
    const int lane = tid & 31;

    if (tid < 64) ws_s[tid] = g_wd_sum[tid];

    float ps = 0.f;
    #pragma unroll
    for (int d = tid; d < 768; d += 128) ps += text[(size_t)bi * 768 + d] * g_wt_sum[d];
    if (tid < 64) ps += pos[(size_t)bi * 64 + tid] * g_wp_sum[tid];
    #pragma unroll
    for (int o = 16; o; o >>= 1) ps += __shfl_xor_sync(0xffffffffu, ps, o);
    if (lane == 0) red[tid >> 5] = ps;
    __syncthreads();
    const float s_base = red[0] + red[1] + red[2] + red[3] + g_bsum;
    __syncthreads();

    const float4* dr = (const float4*)(dep + ((size_t)bi * 128 + tid) * 64);
    float dot = 0.f;
    #pragma unroll
    for (int q = 0; q < 16; q++) {
        float4 v = dr[q];
        dot += v.x * ws_s[4 * q] + v.y * ws_s[4 * q + 1] + v.z * ws_s[4 * q + 2] + v.w * ws_s[4 * q + 3];
        int base = tid * 65 + 4 * q;
        dep_s[base]     = v.x;
        dep_s[base + 1] = v.y;
        dep_s[base + 2] = v.z;
        dep_s[base + 3] = v.w;
    }
    const float score = s_base + dot + (adj[(size_t)bi * 128 + tid] == 0 ? NEGC : 0.f);

    float m = score;
    #pragma unroll
    for (int o = 16; o; o >>= 1) m = fmaxf(m, __shfl_xor_sync(0xffffffffu, m, o));
    if (lane == 0) red[tid >> 5] = m;
    __syncthreads();
    const float mx = fmaxf(fmaxf(red[0], red[1]), fmaxf(red[2], red[3]));
    __syncthreads();
    const float e = expf(score - mx);
    float z = e;
    #pragma unroll
    for (int o = 16; o; o >>= 1) z += __shfl_xor_sync(0xffffffffu, z, o);
    if (lane == 0) red[tid >> 5] = z;
    __syncthreads();
    const float Z = red[0] + red[1] + red[2] + red[3];
    const float p = e / Z;
    p_s[tid] = p;
    p_out[(size_t)bi * 128 + tid] = p;
    __syncthreads();

    // coalesced tf32-rounded dep copy for kernel_r (STG.128)
    #pragma unroll
    for (int it = 0; it < 16; it++) {
        int idx4 = tid + it * 128;            // 0..2047 float4s
        int j = idx4 >> 4, c4 = idx4 & 15;
        const float* rowp = dep_s + j * 65 + c4 * 4;
        float4 wv = make_float4(to_tf32(rowp[0]), to_tf32(rowp[1]),
                                to_tf32(rowp[2]), to_tf32(rowp[3]));
        *(float4*)(g_depc + (size_t)bi * 8192 + (size_t)idx4 * 4) = wv;
    }

    const int half = tid >> 6, k = tid & 63;
    float s = 0.f;
    #pragma unroll 4
    for (int j = half * 64; j < half * 64 + 64; j++) s += p_s[j] * dep_s[j * 65 + k];
    red[tid] = s;
    __syncthreads();
    if (tid < 64) g_pd[(size_t)bi * 64 + tid] = red[tid] + red[tid + 64];
}

// ---------------- kernel R: r = dep @ Wd_attn + A  (persistent, 2 CTAs/SM) ----------------
// grid (6, 49) = 294 CTAs (2 per SM). 256 thr = 8 warps (2 wm x 4 wn), warp tile 64x32.
// N-tile = 128 cols. dep double-buffered via cp.async from g_depc (pre-rounded tf32).
// Wd slice [64x128] loaded once per CTA, column-permuted for STG.128 epilogue.
constexpr int SD      = 68;                  // dep_s row stride (mod32==4)
constexpr int SBW     = 136;                 // wd_s row stride (mod32==8)
constexpr int DEPF    = 128 * SD;            // 8704 floats per dep buffer
constexpr int WDF     = 64 * SBW;            // 8704 floats
constexpr int R_SMEMF = 2 * DEPF + WDF + 2 * 128;   // 26368 floats
constexpr int R_SMEMB = R_SMEMF * 4;         // 105472 bytes
constexpr int NCH     = 49;

__global__ void __launch_bounds__(256, 2) kernel_r(
    const float* __restrict__ depc, const float* __restrict__ Wda,
    float* __restrict__ rout) {

    extern __shared__ float sm[];
    float* dep_b[2] = { sm, sm + DEPF };
    float* wd_s     = sm + 2 * DEPF;
    float* a_b[2]   = { wd_s + WDF, wd_s + WDF + 128 };
    const uint32_t s_dep0 = (uint32_t)__cvta_generic_to_shared(dep_b[0]);
    const uint32_t s_dep1 = (uint32_t)__cvta_generic_to_shared(dep_b[1]);
    const uint32_t s_a0   = (uint32_t)__cvta_generic_to_shared(a_b[0]);
    const uint32_t s_a1   = (uint32_t)__cvta_generic_to_shared(a_b[1]);

    const int tid = threadIdx.x;
    const int nt  = blockIdx.x;   // 0..5 N-tile of 128 cols

    // ---- Wd_attn slice [64 x 128] -> row-major (k), column-permuted, rna tf32 (once) ----
    // actual col A = 16q+4T+d -> logical L = 16q + 8*(d>>1) + 2T + (d&1)
    #pragma unroll
    for (int it = 0; it < 8; it++) {
        int idx = tid + it * 256;
        int k = idx >> 5, c4 = idx & 31;
        float4 v = *(const float4*)(Wda + (size_t)k * 768 + nt * 128 + c4 * 4);
        int A  = c4 * 4;
        int L0 = (A & ~15) + (((A >> 2) & 3) << 1);
        *(float2*)(wd_s + k * SBW + L0)     = make_float2(to_tf32(v.x), to_tf32(v.y));
        *(float2*)(wd_s + k * SBW + L0 + 8) = make_float2(to_tf32(v.z), to_tf32(v.w));
    }

    const int w  = tid >> 5, lane = tid & 31;
    const int g  = lane >> 2, t = lane & 3;
    const int wm = w >> 2, wn = w & 3;   // 2 x 4 warps; warp tile 64 x 32

    // cp.async issue for one bi into buffer buf
    auto issue = [&](int bi_, int buf) {
        const float4* src = (const float4*)(depc + (size_t)bi_ * 8192);
        const uint32_t db = buf ? s_dep1 : s_dep0;
        #pragma unroll
        for (int it = 0; it < 8; it++) {
            int idx = tid + it * 256;
            int j = idx >> 4, c4 = idx & 15;
            cpasync16(db + (uint32_t)(j * SD + c4 * 4) * 4, src + idx);
        }
        if (tid < 32)
            cpasync16((buf ? s_a1 : s_a0) + (uint32_t)tid * 16,
                      (const float4*)(g_A + (size_t)bi_ * 768 + nt * 128) + tid);
        cp_commit();
    };

    int bi = blockIdx.y;
    issue(bi, 0);
    int cur = 0;

    while (true) {
        const int bin = bi + NCH;
        if (bin < 1024) { issue(bin, cur ^ 1); cp_wait<1>(); }
        else            { cp_wait<0>(); }
        __syncthreads();          // buffer `cur` (and wd_s on iter 0) ready for all

        const float* dep_s = dep_b[cur];
        const float* a_s   = a_b[cur];

        float acc[4][4][4];
        #pragma unroll
        for (int mf = 0; mf < 4; mf++)
            #pragma unroll
            for (int nf = 0; nf < 4; nf++)
                #pragma unroll
                for (int q = 0; q < 4; q++) acc[mf][nf][q] = 0.f;

        #pragma unroll
        for (int ks = 0; ks < 8; ks++) {
            const int kb = ks * 8;
            uint32_t a[4][4], b[4][2];
            #pragma unroll
            for (int mf = 0; mf < 4; mf++) {
                int r = wm * 64 + mf * 16 + g;
                a[mf][0] = __float_as_uint(dep_s[r * SD + kb + t]);
                a[mf][1] = __float_as_uint(dep_s[(r + 8) * SD + kb + t]);
                a[mf][2] = __float_as_uint(dep_s[r * SD + kb + 4 + t]);
                a[mf][3] = __float_as_uint(dep_s[(r + 8) * SD + kb + 4 + t]);
            }
            #pragma unroll
            for (int nf = 0; nf < 4; nf++) {
                int c = wn * 32 + nf * 8 + g;   // logical column
                b[nf][0] = __float_as_uint(wd_s[(kb + t) * SBW + c]);
                b[nf][1] = __float_as_uint(wd_s[(kb + 4 + t) * SBW + c]);
            }
            #pragma unroll
            for (int mf = 0; mf < 4; mf++)
                #pragma unroll
                for (int nf = 0; nf < 4; nf++) mma8(acc[mf][nf], a[mf], b[nf]);
        }

        // epilogue: +A, STG.128 streaming stores on actual (de-permuted) columns
        float* rbase = rout + (size_t)bi * 98304 + nt * 128;
        #pragma unroll
        for (int mf = 0; mf < 4; mf++) {
            #pragma unroll
            for (int q2 = 0; q2 < 2; q2++) {
                int r0  = wm * 64 + mf * 16 + g;
                int col = wn * 32 + (q2 << 4) + 4 * t;
                float4 a4 = *(const float4*)(a_s + col);
                float4 w0 = make_float4(acc[mf][2 * q2][0] + a4.x, acc[mf][2 * q2][1] + a4.y,
                                        acc[mf][2 * q2 + 1][0] + a4.z, acc[mf][2 * q2 + 1][1] + a4.w);
                float4 w1 = make_float4(acc[mf][2 * q2][2] + a4.x, acc[mf][2 * q2][3] + a4.y,
                                        acc[mf][2 * q2 + 1][2] + a4.z, acc[mf][2 * q2 + 1][3] + a4.w);
                __stcs((float4*)(rbase + (size_t)r0 * 768 + col), w0);
                __stcs((float4*)(rbase + (size_t)(r0 + 8) * 768 + col), w1);
            }
        }

        bi = bin;
        if (bi >= 1024) break;
        cur ^= 1;
        __syncthreads();   // all readers done before next issue overwrites the other buffer
    }
}

// ---------------- launch ----------------
extern "C" void kernel_launch(void* const* d_in, const int* in_sizes, int n_in,
                              void* d_out, int out_size) {
    const float* text = (const float*)d_in[0];
    const int*   adj  = (const int*)d_in[1];
    const float* dep  = (const float*)d_in[2];
    const float* pos  = (const float*)d_in[3];
    const float* Wt   = (const float*)d_in[4];
    const float* Wpa  = (const float*)d_in[5];
    const float* Wda  = (const float*)d_in[6];
    const float* ba   = (const float*)d_in[7];
    const float* Wd   = (const float*)d_in[8];
    const float* bd   = (const float*)d_in[9];
    const float* Wp   = (const float*)d_in[10];
    const float* bp   = (const float*)d_in[11];
    float* out = (float*)d_out;

    cudaFuncSetAttribute(kernel_r, cudaFuncAttributeMaxDynamicSharedMemorySize, R_SMEMB);

    float* depc_ptr;
    cudaGetSymbolAddress((void**)&depc_ptr, g_depc);

    // 1) row sums + combined bias
    k0_sums<<<116, 256>>>(Wt, Wpa, Wda, ba, bd, bp);
    // 2) A = text@Wt + pos@Wp_attn + b_attn  -> g_A
    gemm_small<<<dim3(6, 16), 128>>>(text, 768, Wt, 768, pos, 64, Wpa, 64,
                                     /*use_pd=*/0, ba, nullptr, nullptr);
    // 3) scores/softmax -> p (out), g_pd, and tf32-rounded dep copy -> g_depc
    kernel_s<<<BI, 128>>>(text, adj, dep, pos, out + P_OFF);
    // 4) r = dep@Wd_attn + A  -> out[0 : R_SIZE)   (persistent, 2 CTAs/SM)
    kernel_r<<<dim3(6, NCH), 256, R_SMEMB>>>(depc_ptr, Wda, out);
    // 5) output_sum = pos@Wp + g_pd@Wd + (bp+bd) + text -> out[OS_OFF : )
    gemm_small<<<dim3(6, 16), 128>>>(pos, 64, Wp, 64, nullptr, 64, Wd, 64,
                                     /*use_pd=*/1, nullptr, text, out + OS_OFF);
}

// round 9
// speedup vs baseline: 1.2385x; 1.0541x over previous
#include <cuda_runtime.h>
#include <cstdint>
#include <cstddef>

// ---------------- problem constants ----------------
constexpr int Bb   = 8;
constexpr int Ll   = 128;
constexpr int Dd   = 768;
constexpr int DEP  = 64;
constexpr int POSN = 64;
constexpr int OUTN = 768;
constexpr int BI   = Bb * Ll;                       // 1024 (b,i) rows
constexpr long long R_SIZE = (long long)BI * Ll * OUTN;   // 100663296
constexpr long long OS_OFF = R_SIZE;                       // output_sum offset
constexpr long long P_OFF  = R_SIZE + (long long)BI * OUTN; // p offset
#define NEGC (-1e30f)

// ---------------- scratch (device globals; no allocs) ----------------
__device__ __align__(16) float g_A[BI * OUTN];     // A[b,i,o]
__device__ __align__(16) float g_pd[BI * DEP];     // sum_j p * dep
__device__ __align__(16) float g_depc[(size_t)BI * 128 * 64]; // tf32-rounded dep (33.5 MB)
__device__ float g_wt_sum[Dd];
__device__ float g_wp_sum[POSN];
__device__ float g_wd_sum[DEP];
__device__ float g_bias_out[OUTN];                 // bp + bd
__device__ float g_bsum;                           // sum(b_attn)

// ---------------- helpers ----------------
__device__ __forceinline__ float to_tf32(float x) {
    uint32_t u;
    asm("cvt.rna.tf32.f32 %0, %1;" : "=r"(u) : "f"(x));
    return __uint_as_float(u);
}
__device__ __forceinline__ void mma8(float c[4], const uint32_t a[4], const uint32_t b[2]) {
    asm volatile(
        "mma.sync.aligned.m16n8k8.row.col.f32.tf32.tf32.f32 "
        "{%0,%1,%2,%3},{%4,%5,%6,%7},{%8,%9},{%0,%1,%2,%3};\n"
        : "+f"(c[0]), "+f"(c[1]), "+f"(c[2]), "+f"(c[3])
        : "r"(a[0]), "r"(a[1]), "r"(a[2]), "r"(a[3]), "r"(b[0]), "r"(b[1]));
}
__device__ __forceinline__ void cpasync16(uint32_t dst, const void* src) {
    asm volatile("cp.async.cg.shared.global [%0], [%1], 16;\n" :: "r"(dst), "l"(src));
}
__device__ __forceinline__ void cp_commit() {
    asm volatile("cp.async.commit_group;\n" ::: "memory");
}
template <int N>
__device__ __forceinline__ void cp_wait() {
    asm volatile("cp.async.wait_group %0;\n" :: "n"(N) : "memory");
}

// ---------------- K0: row sums + combined bias (warp-per-row) ----------------
__global__ void k0_sums(const float* __restrict__ Wt, const float* __restrict__ Wpa,
                        const float* __restrict__ Wda, const float* __restrict__ b_attn,
                        const float* __restrict__ bd, const float* __restrict__ bp) {
    const int gw   = (blockIdx.x * blockDim.x + threadIdx.x) >> 5;
    const int lane = threadIdx.x & 31;
    if (gw <= 896) {
        const float* src;
        if (gw < 768)      src = Wt  + (size_t)gw * 768;
        else if (gw < 832) src = Wpa + (size_t)(gw - 768) * 768;
        else if (gw < 896) src = Wda + (size_t)(gw - 832) * 768;
        else               src = b_attn;
        const float4* p4 = (const float4*)src;
        float s = 0.f;
        #pragma unroll
        for (int i = 0; i < 6; i++) { float4 v = p4[lane + i * 32]; s += v.x + v.y + v.z + v.w; }
        #pragma unroll
        for (int o = 16; o; o >>= 1) s += __shfl_xor_sync(0xffffffffu, s, o);
        if (lane == 0) {
            if (gw < 768)      g_wt_sum[gw] = s;
            else if (gw < 832) g_wp_sum[gw - 768] = s;
            else if (gw < 896) g_wd_sum[gw - 832] = s;
            else               g_bsum = s;
        }
    } else if (gw >= 897 && gw < 921) {
        int n = (gw - 897) * 32 + lane;
        g_bias_out[n] = bp[n] + bd[n];
    }
}

// ---------------- gemm_small (R6 version): BM=64, BN=128, BK=32, 4 warps ----------------
__global__ void __launch_bounds__(128) gemm_small(
    const float* __restrict__ A1, int lda1, const float* __restrict__ B1, int K1,
    const float* __restrict__ A2_, int lda2, const float* __restrict__ B2, int K2,
    int use_pd, const float* __restrict__ bias_, const float* __restrict__ addend,
    float* __restrict__ out_) {

    __shared__ float a_sm[64 * 36];
    __shared__ float b_sm[32 * 136];
    __shared__ float bias_s[128];

    const int tid   = threadIdx.x;
    const int nbase = blockIdx.x * 128;
    const int mbase = blockIdx.y * 64;
    const float* A2   = use_pd ? g_pd : A2_;
    float*       out  = out_ ? out_ : g_A;
    const float* bias = bias_ ? bias_ : g_bias_out;

    bias_s[tid] = bias[nbase + tid];

    const int w  = tid >> 5, lane = tid & 31;
    const int g  = lane >> 2, t = lane & 3;
    const int wm = w >> 1, wn = w & 1;

    float acc[2][8][4];
    #pragma unroll
    for (int mf = 0; mf < 2; mf++)
        #pragma unroll
        for (int nf = 0; nf < 8; nf++)
            #pragma unroll
            for (int q = 0; q < 4; q++) acc[mf][nf][q] = 0.f;

    #pragma unroll
    for (int s = 0; s < 2; s++) {
        const float* Ap = s ? A2 : A1;
        const float* Bp = s ? B2 : B1;
        const int lda   = s ? lda2 : lda1;
        const int Ks    = s ? K2 : K1;
        for (int kt = 0; kt < Ks; kt += 32) {
            #pragma unroll
            for (int it = 0; it < 4; it++) {
                int idx = tid + it * 128;
                int row = idx >> 3, k4 = idx & 7;
                float4 v = *(const float4*)(Ap + (size_t)(mbase + row) * lda + kt + k4 * 4);
                float4 wv = make_float4(to_tf32(v.x), to_tf32(v.y), to_tf32(v.z), to_tf32(v.w));
                *(float4*)(a_sm + row * 36 + k4 * 4) = wv;
            }
            #pragma unroll
            for (int it = 0; it < 8; it++) {
                int idx = tid + it * 128;
                int kr = idx >> 5, c4 = idx & 31;
                float4 v = *(const float4*)(Bp + (size_t)(kt + kr) * 768 + nbase + c4 * 4);
                float4 wv = make_float4(to_tf32(v.x), to_tf32(v.y), to_tf32(v.z), to_tf32(v.w));
                *(float4*)(b_sm + kr * 136 + c4 * 4) = wv;
            }
            __syncthreads();
            #pragma unroll
            for (int ks = 0; ks < 4; ks++) {
                const int kb = ks * 8;
                uint32_t a[2][4], b[8][2];
                #pragma unroll
                for (int mf = 0; mf < 2; mf++) {
                    int r = wm * 32 + mf * 16 + g;
                    a[mf][0] = __float_as_uint(a_sm[r * 36 + kb + t]);
                    a[mf][1] = __float_as_uint(a_sm[(r + 8) * 36 + kb + t]);
                    a[mf][2] = __float_as_uint(a_sm[r * 36 + kb + 4 + t]);
                    a[mf][3] = __float_as_uint(a_sm[(r + 8) * 36 + kb + 4 + t]);
                }
                #pragma unroll
                for (int nf = 0; nf < 8; nf++) {
                    int c = wn * 64 + nf * 8 + g;
                    b[nf][0] = __float_as_uint(b_sm[(kb + t) * 136 + c]);
                    b[nf][1] = __float_as_uint(b_sm[(kb + 4 + t) * 136 + c]);
                }
                #pragma unroll
                for (int mf = 0; mf < 2; mf++)
                    #pragma unroll
                    for (int nf = 0; nf < 8; nf++) mma8(acc[mf][nf], a[mf], b[nf]);
            }
            __syncthreads();
        }
    }

    #pragma unroll
    for (int mf = 0; mf < 2; mf++) {
        #pragma unroll
        for (int nf = 0; nf < 8; nf++) {
            int r0 = mbase + wm * 32 + mf * 16 + g;
            int cl = wn * 64 + nf * 8 + 2 * t;
            int c  = nbase + cl;
            float a0 = 0.f, a1 = 0.f, a2 = 0.f, a3 = 0.f;
            if (addend) {
                a0 = addend[(size_t)r0 * 768 + c];
                a1 = addend[(size_t)r0 * 768 + c + 1];
                a2 = addend[(size_t)(r0 + 8) * 768 + c];
                a3 = addend[(size_t)(r0 + 8) * 768 + c + 1];
            }
            float2 v0 = make_float2(acc[mf][nf][0] + bias_s[cl] + a0,
                                    acc[mf][nf][1] + bias_s[cl + 1] + a1);
            float2 v1 = make_float2(acc[mf][nf][2] + bias_s[cl] + a2,
                                    acc[mf][nf][3] + bias_s[cl + 1] + a3);
            *(float2*)(out + (size_t)r0 * 768 + c) = v0;
            *(float2*)(out + (size_t)(r0 + 8) * 768 + c) = v1;
        }
    }
}

// ---------------- kernel S: scores + softmax + p + p-weighted dep + tf32 dep copy ----------------
__global__ void __launch_bounds__(128) kernel_s(
    const float* __restrict__ text, const int* __restrict__ adj,
    const float* __restrict__ dep, const float* __restrict__ pos,
    float* __restrict__ p_out) {

    __shared__ float dep_s[128 * 65];
    __shared__ float ws_s[64];
    __shared__ float p_s[128];
    __shared__ float red[128];

    const int bi  = blockIdx.x;
    const int tid = threadIdx.x;
    const int lane = tid & 31;

    if (tid < 64) ws_s[tid] = g_wd_sum[tid];

    float ps = 0.f;
    #pragma unroll
    for (int d = tid; d < 768; d += 128) ps += text[(size_t)bi * 768 + d] * g_wt_sum[d];
    if (tid < 64) ps += pos[(size_t)bi * 64 + tid] * g_wp_sum[tid];
    #pragma unroll
    for (int o = 16; o; o >>= 1) ps += __shfl_xor_sync(0xffffffffu, ps, o);
    if (lane == 0) red[tid >> 5] = ps;
    __syncthreads();
    const float s_base = red[0] + red[1] + red[2] + red[3] + g_bsum;
    __syncthreads();

    const float4* dr = (const float4*)(dep + ((size_t)bi * 128 + tid) * 64);
    float dot = 0.f;
    #pragma unroll
    for (int q = 0; q < 16; q++) {
        float4 v = dr[q];
        dot += v.x * ws_s[4 * q] + v.y * ws_s[4 * q + 1] + v.z * ws_s[4 * q + 2] + v.w * ws_s[4 * q + 3];
        int base = tid * 65 + 4 * q;
        dep_s[base]     = v.x;
        dep_s[base + 1] = v.y;
        dep_s[base + 2] = v.z;
        dep_s[base + 3] = v.w;
    }
    const float score = s_base + dot + (adj[(size_t)bi * 128 + tid] == 0 ? NEGC : 0.f);

    float m = score;
    #pragma unroll
    for (int o = 16; o; o >>= 1) m = fmaxf(m, __shfl_xor_sync(0xffffffffu, m, o));
    if (lane == 0) red[tid >> 5] = m;
    __syncthreads();
    const float mx = fmaxf(fmaxf(red[0], red[1]), fmaxf(red[2], red[3]));
    __syncthreads();
    const float e = expf(score - mx);
    float z = e;
    #pragma unroll
    for (int o = 16; o; o >>= 1) z += __shfl_xor_sync(0xffffffffu, z, o);
    if (lane == 0) red[tid >> 5] = z;
    __syncthreads();
    const float Z = red[0] + red[1] + red[2] + red[3];
    const float p = e / Z;
    p_s[tid] = p;
    p_out[(size_t)bi * 128 + tid] = p;
    __syncthreads();

    // coalesced tf32-rounded dep copy for kernel_r (STG.128)
    #pragma unroll
    for (int it = 0; it < 16; it++) {
        int idx4 = tid + it * 128;            // 0..2047 float4s
        int j = idx4 >> 4, c4 = idx4 & 15;
        const float* rowp = dep_s + j * 65 + c4 * 4;
        float4 wv = make_float4(to_tf32(rowp[0]), to_tf32(rowp[1]),
                                to_tf32(rowp[2]), to_tf32(rowp[3]));
        *(float4*)(g_depc + (size_t)bi * 8192 + (size_t)idx4 * 4) = wv;
    }

    const int half = tid >> 6, k = tid & 63;
    float s = 0.f;
    #pragma unroll 4
    for (int j = half * 64; j < half * 64 + 64; j++) s += p_s[j] * dep_s[j * 65 + k];
    red[tid] = s;
    __syncthreads();
    if (tid < 64) g_pd[(size_t)bi * 64 + tid] = red[tid] + red[tid + 64];
}

// ---------------- kernel R: r = dep @ Wd_attn + A  (persistent, triple-buffered cp.async) ----------------
// grid (3, 49) = 147 CTAs (one wave, 1 CTA/SM). 256 thr = 8 warps (2 wm x 4 wn),
// warp tile 64x64 (R6-proven geometry/layout). dep tiles stream from g_depc
// (pre-rounded tf32, L2-resident) via cp.async into a 3-deep ring -> exactly ONE
// __syncthreads per iteration; loads fully off the thread critical path.
constexpr int SD      = 68;                  // dep_s row stride (mod32==4)
constexpr int SBW     = 264;                 // wd_s row stride (mod32==8)
constexpr int DEPF    = 128 * SD;            // 8704 floats per dep buffer
constexpr int WDF     = 64 * SBW;            // 16896 floats
constexpr int R_SMEMF = 3 * DEPF + WDF + 3 * 256;   // 43776 floats
constexpr int R_SMEMB = R_SMEMF * 4;         // 175104 bytes
constexpr int NCH     = 49;

__global__ void __launch_bounds__(256, 1) kernel_r(
    const float* __restrict__ depc, const float* __restrict__ Wda,
    float* __restrict__ rout) {

    extern __shared__ float sm[];
    float* dep_b0 = sm;
    float* wd_s   = sm + 3 * DEPF;
    float* a_b0   = wd_s + WDF;
    uint32_t s_dep[3], s_a[3];
    #pragma unroll
    for (int q = 0; q < 3; q++) {
        s_dep[q] = (uint32_t)__cvta_generic_to_shared(dep_b0 + q * DEPF);
        s_a[q]   = (uint32_t)__cvta_generic_to_shared(a_b0 + q * 256);
    }

    const int tid = threadIdx.x;
    const int nt  = blockIdx.x;   // 0..2 N-tile of 256 cols

    // cp.async issue of one bi's dep tile + A row into ring slot `buf`
    auto issue = [&](int bi_, int buf) {
        const float4* src = (const float4*)(depc + (size_t)bi_ * 8192);
        const uint32_t db = s_dep[buf];
        #pragma unroll
        for (int it = 0; it < 8; it++) {
            int idx = tid + it * 256;
            int j = idx >> 4, c4 = idx & 15;
            cpasync16(db + (uint32_t)(j * SD + c4 * 4) * 4, src + idx);
        }
        if (tid < 64)
            cpasync16(s_a[buf] + (uint32_t)tid * 16,
                      (const float4*)(g_A + (size_t)bi_ * 768 + nt * 256) + tid);
        cp_commit();
    };

    int bi = blockIdx.y;
    issue(bi, 0);                 // slot 0 in flight

    // ---- Wd_attn slice [64 x 256], column-permuted for STG.128 epilogue (once) ----
    // actual col A = 16q+4T+d -> logical L = 16q + 8*(d>>1) + 2T + (d&1)
    #pragma unroll
    for (int it = 0; it < 16; it++) {
        int idx = tid + it * 256;
        int k = idx >> 6, c4 = idx & 63;
        float4 v = *(const float4*)(Wda + (size_t)k * 768 + nt * 256 + c4 * 4);
        int A  = c4 * 4;
        int L0 = (A & ~15) + (((A >> 2) & 3) << 1);
        *(float2*)(wd_s + k * SBW + L0)     = make_float2(to_tf32(v.x), to_tf32(v.y));
        *(float2*)(wd_s + k * SBW + L0 + 8) = make_float2(to_tf32(v.z), to_tf32(v.w));
    }

    const int w  = tid >> 5, lane = tid & 31;
    const int g  = lane >> 2, t = lane & 3;
    const int wm = w >> 2, wn = w & 3;   // 2 x 4 warps; warp tile 64 x 64

    int cur = 0;
    while (true) {
        const int bin = bi + NCH;
        if (bin < 1024) { issue(bin, cur == 2 ? 0 : cur + 1); cp_wait<1>(); }
        else            { cp_wait<0>(); }
        __syncthreads();   // slot `cur` (and wd_s on iter 0) visible to all warps

        const float* dep_s = dep_b0 + cur * DEPF;
        const float* a_s   = a_b0 + cur * 256;

        float acc[4][8][4];
        #pragma unroll
        for (int mf = 0; mf < 4; mf++)
            #pragma unroll
            for (int nf = 0; nf < 8; nf++)
                #pragma unroll
                for (int q = 0; q < 4; q++) acc[mf][nf][q] = 0.f;

        #pragma unroll
        for (int ks = 0; ks < 8; ks++) {
            const int kb = ks * 8;
            uint32_t a[4][4], b[8][2];
            #pragma unroll
            for (int mf = 0; mf < 4; mf++) {
                int r = wm * 64 + mf * 16 + g;
                a[mf][0] = __float_as_uint(dep_s[r * SD + kb + t]);
                a[mf][1] = __float_as_uint(dep_s[(r + 8) * SD + kb + t]);
                a[mf][2] = __float_as_uint(dep_s[r * SD + kb + 4 + t]);
                a[mf][3] = __float_as_uint(dep_s[(r + 8) * SD + kb + 4 + t]);
            }
            #pragma unroll
            for (int nf = 0; nf < 8; nf++) {
                int c = wn * 64 + nf * 8 + g;   // logical column
                b[nf][0] = __float_as_uint(wd_s[(kb + t) * SBW + c]);
                b[nf][1] = __float_as_uint(wd_s[(kb + 4 + t) * SBW + c]);
            }
            #pragma unroll
            for (int mf = 0; mf < 4; mf++)
                #pragma unroll
                for (int nf = 0; nf < 8; nf++) mma8(acc[mf][nf], a[mf], b[nf]);
        }

        // epilogue: +A, STG.128 streaming stores on actual (de-permuted) columns
        float* rbase = rout + (size_t)bi * 98304 + nt * 256;
        #pragma unroll
        for (int mf = 0; mf < 4; mf++) {
            #pragma unroll
            for (int q2 = 0; q2 < 4; q2++) {
                int r0  = wm * 64 + mf * 16 + g;
                int col = wn * 64 + (q2 << 4) + 4 * t;
                float4 a4 = *(const float4*)(a_s + col);
                float4 w0 = make_float4(acc[mf][2 * q2][0] + a4.x, acc[mf][2 * q2][1] + a4.y,
                                        acc[mf][2 * q2 + 1][0] + a4.z, acc[mf][2 * q2 + 1][1] + a4.w);
                float4 w1 = make_float4(acc[mf][2 * q2][2] + a4.x, acc[mf][2 * q2][3] + a4.y,
                                        acc[mf][2 * q2 + 1][2] + a4.z, acc[mf][2 * q2 + 1][3] + a4.w);
                __stcs((float4*)(rbase + (size_t)r0 * 768 + col), w0);
                __stcs((float4*)(rbase + (size_t)(r0 + 8) * 768 + col), w1);
            }
        }

        bi = bin;
        if (bi >= 1024) break;
        cur = (cur == 2) ? 0 : cur + 1;
    }
}

// ---------------- launch ----------------
extern "C" void kernel_launch(void* const* d_in, const int* in_sizes, int n_in,
                              void* d_out, int out_size) {
    const float* text = (const float*)d_in[0];
    const int*   adj  = (const int*)d_in[1];
    const float* dep  = (const float*)d_in[2];
    const float* pos  = (const float*)d_in[3];
    const float* Wt   = (const float*)d_in[4];
    const float* Wpa  = (const float*)d_in[5];
    const float* Wda  = (const float*)d_in[6];
    const float* ba   = (const float*)d_in[7];
    const float* Wd   = (const float*)d_in[8];
    const float* bd   = (const float*)d_in[9];
    const float* Wp   = (const float*)d_in[10];
    const float* bp   = (const float*)d_in[11];
    float* out = (float*)d_out;

    cudaFuncSetAttribute(kernel_r, cudaFuncAttributeMaxDynamicSharedMemorySize, R_SMEMB);

    float* depc_ptr;
    cudaGetSymbolAddress((void**)&depc_ptr, g_depc);

    // 1) row sums + combined bias
    k0_sums<<<116, 256>>>(Wt, Wpa, Wda, ba, bd, bp);
    // 2) A = text@Wt + pos@Wp_attn + b_attn  -> g_A
    gemm_small<<<dim3(6, 16), 128>>>(text, 768, Wt, 768, pos, 64, Wpa, 64,
                                     /*use_pd=*/0, ba, nullptr, nullptr);
    // 3) scores/softmax -> p (out), g_pd, and tf32-rounded dep copy -> g_depc
    kernel_s<<<BI, 128>>>(text, adj, dep, pos, out + P_OFF);
    // 4) r = dep@Wd_attn + A  -> out[0 : R_SIZE)   (persistent, triple-buffered)
    kernel_r<<<dim3(3, NCH), 256, R_SMEMB>>>(depc_ptr, Wda, out);
    // 5) output_sum = pos@Wp + g_pd@Wd + (bp+bd) + text -> out[OS_OFF : )
    gemm_small<<<dim3(6, 16), 128>>>(pos, 64, Wp, 64, nullptr, 64, Wd, 64,
                                     /*use_pd=*/1, nullptr, text, out + OS_OFF);
}

// round 10
// speedup vs baseline: 1.2918x; 1.0430x over previous
#include <cuda_runtime.h>
#include <cstdint>
#include <cstddef>

// ---------------- problem constants ----------------
constexpr int Bb   = 8;
constexpr int Ll   = 128;
constexpr int Dd   = 768;
constexpr int DEP  = 64;
constexpr int POSN = 64;
constexpr int OUTN = 768;
constexpr int BI   = Bb * Ll;                       // 1024 (b,i) rows
constexpr long long R_SIZE = (long long)BI * Ll * OUTN;   // 100663296
constexpr long long OS_OFF = R_SIZE;                       // output_sum offset
constexpr long long P_OFF  = R_SIZE + (long long)BI * OUTN; // p offset
#define NEGC (-1e30f)

// ---------------- scratch (device globals; no allocs) ----------------
__device__ __align__(16) float g_A[BI * OUTN];     // A[b,i,o]
__device__ __align__(16) float g_pd[BI * DEP];     // sum_j p * dep
__device__ __align__(16) float g_depc[(size_t)BI * 128 * 64]; // tf32-rounded dep (33.5 MB)
__device__ float g_wt_sum[Dd];
__device__ float g_wp_sum[POSN];
__device__ float g_wd_sum[DEP];
__device__ float g_bias_out[OUTN];                 // bp + bd
__device__ float g_bsum;                           // sum(b_attn)

// ---------------- helpers ----------------
__device__ __forceinline__ float to_tf32(float x) {
    uint32_t u;
    asm("cvt.rna.tf32.f32 %0, %1;" : "=r"(u) : "f"(x));
    return __uint_as_float(u);
}
__device__ __forceinline__ void mma8(float c[4], const uint32_t a[4], const uint32_t b[2]) {
    asm volatile(
        "mma.sync.aligned.m16n8k8.row.col.f32.tf32.tf32.f32 "
        "{%0,%1,%2,%3},{%4,%5,%6,%7},{%8,%9},{%0,%1,%2,%3};\n"
        : "+f"(c[0]), "+f"(c[1]), "+f"(c[2]), "+f"(c[3])
        : "r"(a[0]), "r"(a[1]), "r"(a[2]), "r"(a[3]), "r"(b[0]), "r"(b[1]));
}
__device__ __forceinline__ void cpasync16(uint32_t dst, const void* src) {
    asm volatile("cp.async.cg.shared.global [%0], [%1], 16;\n" :: "r"(dst), "l"(src));
}
__device__ __forceinline__ void cp_commit() {
    asm volatile("cp.async.commit_group;\n" ::: "memory");
}
template <int N>
__device__ __forceinline__ void cp_wait() {
    asm volatile("cp.async.wait_group %0;\n" :: "n"(N) : "memory");
}

// ---------------- K0: row sums + combined bias (warp-per-row) ----------------
__global__ void k0_sums(const float* __restrict__ Wt, const float* __restrict__ Wpa,
                        const float* __restrict__ Wda, const float* __restrict__ b_attn,
                        const float* __restrict__ bd, const float* __restrict__ bp) {
    const int gw   = (blockIdx.x * blockDim.x + threadIdx.x) >> 5;
    const int lane = threadIdx.x & 31;
    if (gw <= 896) {
        const float* src;
        if (gw < 768)      src = Wt  + (size_t)gw * 768;
        else if (gw < 832) src = Wpa + (size_t)(gw - 768) * 768;
        else if (gw < 896) src = Wda + (size_t)(gw - 832) * 768;
        else               src = b_attn;
        const float4* p4 = (const float4*)src;
        float s = 0.f;
        #pragma unroll
        for (int i = 0; i < 6; i++) { float4 v = p4[lane + i * 32]; s += v.x + v.y + v.z + v.w; }
        #pragma unroll
        for (int o = 16; o; o >>= 1) s += __shfl_xor_sync(0xffffffffu, s, o);
        if (lane == 0) {
            if (gw < 768)      g_wt_sum[gw] = s;
            else if (gw < 832) g_wp_sum[gw - 768] = s;
            else if (gw < 896) g_wd_sum[gw - 832] = s;
            else               g_bsum = s;
        }
    } else if (gw >= 897 && gw < 921) {
        int n = (gw - 897) * 32 + lane;
        g_bias_out[n] = bp[n] + bd[n];
    }
}

// ---------------- gemm_small (R6 version): BM=64, BN=128, BK=32, 4 warps ----------------
__global__ void __launch_bounds__(128) gemm_small(
    const float* __restrict__ A1, int lda1, const float* __restrict__ B1, int K1,
    const float* __restrict__ A2_, int lda2, const float* __restrict__ B2, int K2,
    int use_pd, const float* __restrict__ bias_, const float* __restrict__ addend,
    float* __restrict__ out_) {

    __shared__ float a_sm[64 * 36];
    __shared__ float b_sm[32 * 136];
    __shared__ float bias_s[128];

    const int tid   = threadIdx.x;
    const int nbase = blockIdx.x * 128;
    const int mbase = blockIdx.y * 64;
    const float* A2   = use_pd ? g_pd : A2_;
    float*       out  = out_ ? out_ : g_A;
    const float* bias = bias_ ? bias_ : g_bias_out;

    bias_s[tid] = bias[nbase + tid];

    const int w  = tid >> 5, lane = tid & 31;
    const int g  = lane >> 2, t = lane & 3;
    const int wm = w >> 1, wn = w & 1;

    float acc[2][8][4];
    #pragma unroll
    for (int mf = 0; mf < 2; mf++)
        #pragma unroll
        for (int nf = 0; nf < 8; nf++)
            #pragma unroll
            for (int q = 0; q < 4; q++) acc[mf][nf][q] = 0.f;

    #pragma unroll
    for (int s = 0; s < 2; s++) {
        const float* Ap = s ? A2 : A1;
        const float* Bp = s ? B2 : B1;
        const int lda   = s ? lda2 : lda1;
        const int Ks    = s ? K2 : K1;
        for (int kt = 0; kt < Ks; kt += 32) {
            #pragma unroll
            for (int it = 0; it < 4; it++) {
                int idx = tid + it * 128;
                int row = idx >> 3, k4 = idx & 7;
                float4 v = *(const float4*)(Ap + (size_t)(mbase + row) * lda + kt + k4 * 4);
                float4 wv = make_float4(to_tf32(v.x), to_tf32(v.y), to_tf32(v.z), to_tf32(v.w));
                *(float4*)(a_sm + row * 36 + k4 * 4) = wv;
            }
            #pragma unroll
            for (int it = 0; it < 8; it++) {
                int idx = tid + it * 128;
                int kr = idx >> 5, c4 = idx & 31;
                float4 v = *(const float4*)(Bp + (size_t)(kt + kr) * 768 + nbase + c4 * 4);
                float4 wv = make_float4(to_tf32(v.x), to_tf32(v.y), to_tf32(v.z), to_tf32(v.w));
                *(float4*)(b_sm + kr * 136 + c4 * 4) = wv;
            }
            __syncthreads();
            #pragma unroll
            for (int ks = 0; ks < 4; ks++) {
                const int kb = ks * 8;
                uint32_t a[2][4], b[8][2];
                #pragma unroll
                for (int mf = 0; mf < 2; mf++) {
                    int r = wm * 32 + mf * 16 + g;
                    a[mf][0] = __float_as_uint(a_sm[r * 36 + kb + t]);
                    a[mf][1] = __float_as_uint(a_sm[(r + 8) * 36 + kb + t]);
                    a[mf][2] = __float_as_uint(a_sm[r * 36 + kb + 4 + t]);
                    a[mf][3] = __float_as_uint(a_sm[(r + 8) * 36 + kb + 4 + t]);
                }
                #pragma unroll
                for (int nf = 0; nf < 8; nf++) {
                    int c = wn * 64 + nf * 8 + g;
                    b[nf][0] = __float_as_uint(b_sm[(kb + t) * 136 + c]);
                    b[nf][1] = __float_as_uint(b_sm[(kb + 4 + t) * 136 + c]);
                }
                #pragma unroll
                for (int mf = 0; mf < 2; mf++)
                    #pragma unroll
                    for (int nf = 0; nf < 8; nf++) mma8(acc[mf][nf], a[mf], b[nf]);
            }
            __syncthreads();
        }
    }

    #pragma unroll
    for (int mf = 0; mf < 2; mf++) {
        #pragma unroll
        for (int nf = 0; nf < 8; nf++) {
            int r0 = mbase + wm * 32 + mf * 16 + g;
            int cl = wn * 64 + nf * 8 + 2 * t;
            int c  = nbase + cl;
            float a0 = 0.f, a1 = 0.f, a2 = 0.f, a3 = 0.f;
            if (addend) {
                a0 = addend[(size_t)r0 * 768 + c];
                a1 = addend[(size_t)r0 * 768 + c + 1];
                a2 = addend[(size_t)(r0 + 8) * 768 + c];
                a3 = addend[(size_t)(r0 + 8) * 768 + c + 1];
            }
            float2 v0 = make_float2(acc[mf][nf][0] + bias_s[cl] + a0,
                                    acc[mf][nf][1] + bias_s[cl + 1] + a1);
            float2 v1 = make_float2(acc[mf][nf][2] + bias_s[cl] + a2,
                                    acc[mf][nf][3] + bias_s[cl + 1] + a3);
            *(float2*)(out + (size_t)r0 * 768 + c) = v0;
            *(float2*)(out + (size_t)(r0 + 8) * 768 + c) = v1;
        }
    }
}

// ---------------- kernel S: scores + softmax + p + p-weighted dep + tf32 dep copy ----------------
__global__ void __launch_bounds__(128) kernel_s(
    const float* __restrict__ text, const int* __restrict__ adj,
    const float* __restrict__ dep, const float* __restrict__ pos,
    float* __restrict__ p_out) {

    __shared__ float dep_s[128 * 65];
    __shared__ float ws_s[64];
    __shared__ float p_s[128];
    __shared__ float red[128];

    const int bi  = blockIdx.x;
    const int tid = threadIdx.x;
    const int lane = tid & 31;

    if (tid < 64) ws_s[tid] = g_wd_sum[tid];

    float ps = 0.f;
    #pragma unroll
    for (int d = tid; d < 768; d += 128) ps += text[(size_t)bi * 768 + d] * g_wt_sum[d];
    if (tid < 64) ps += pos[(size_t)bi * 64 + tid] * g_wp_sum[tid];
    #pragma unroll
    for (int o = 16; o; o >>= 1) ps += __shfl_xor_sync(0xffffffffu, ps, o);
    if (lane == 0) red[tid >> 5] = ps;
    __syncthreads();
    const float s_base = red[0] + red[1] + red[2] + red[3] + g_bsum;
    __syncthreads();

    const float4* dr = (const float4*)(dep + ((size_t)bi * 128 + tid) * 64);
    float dot = 0.f;
    #pragma unroll
    for (int q = 0; q < 16; q++) {
        float4 v = dr[q];
        dot += v.x * ws_s[4 * q] + v.y * ws_s[4 * q + 1] + v.z * ws_s[4 * q + 2] + v.w * ws_s[4 * q + 3];
        int base = tid * 65 + 4 * q;
        dep_s[base]     = v.x;
        dep_s[base + 1] = v.y;
        dep_s[base + 2] = v.z;
        dep_s[base + 3] = v.w;
    }
    const float score = s_base + dot + (adj[(size_t)bi * 128 + tid] == 0 ? NEGC : 0.f);

    float m = score;
    #pragma unroll
    for (int o = 16; o; o >>= 1) m = fmaxf(m, __shfl_xor_sync(0xffffffffu, m, o));
    if (lane == 0) red[tid >> 5] = m;
    __syncthreads();
    const float mx = fmaxf(fmaxf(red[0], red[1]), fmaxf(red[2], red[3]));
    __syncthreads();
    const float e = expf(score - mx);
    float z = e;
    #pragma unroll
    for (int o = 16; o; o >>= 1) z += __shfl_xor_sync(0xffffffffu, z, o);
    if (lane == 0) red[tid >> 5] = z;
    __syncthreads();
    const float Z = red[0] + red[1] + red[2] + red[3];
    const float p = e / Z;
    p_s[tid] = p;
    p_out[(size_t)bi * 128 + tid] = p;
    __syncthreads();

    // coalesced tf32-rounded dep copy for kernel_r (STG.128)
    #pragma unroll
    for (int it = 0; it < 16; it++) {
        int idx4 = tid + it * 128;            // 0..2047 float4s
        int j = idx4 >> 4, c4 = idx4 & 15;
        const float* rowp = dep_s + j * 65 + c4 * 4;
        float4 wv = make_float4(to_tf32(rowp[0]), to_tf32(rowp[1]),
                                to_tf32(rowp[2]), to_tf32(rowp[3]));
        *(float4*)(g_depc + (size_t)bi * 8192 + (size_t)idx4 * 4) = wv;
    }

    const int half = tid >> 6, k = tid & 63;
    float s = 0.f;
    #pragma unroll 4
    for (int j = half * 64; j < half * 64 + 64; j++) s += p_s[j] * dep_s[j * 65 + k];
    red[tid] = s;
    __syncthreads();
    if (tid < 64) g_pd[(size_t)bi * 64 + tid] = red[tid] + red[tid + 64];
}

// ---------------- kernel R: r = dep @ Wd_attn + A  (persistent, split-N pipelined) ----------------
// grid (3, 49) = 147 CTAs (one wave). 256 thr = 8 warps (2 wm x 4 wn).
// N-tile 256 processed as two 128-col halves: acc is 64 regs, so half-0's STG.128
// burst is in flight while half-1's mma runs, and half-1's stores drain under the
// NEXT iteration's mma (barrier does not wait on STG). dep tiles stream via
// cp.async (3-deep ring) from g_depc (pre-rounded tf32, L2-resident).
constexpr int SD      = 68;                  // dep_s row stride (mod32==4)
constexpr int SBW     = 264;                 // wd_s row stride (mod32==8)
constexpr int DEPF    = 128 * SD;            // 8704 floats per dep buffer
constexpr int WDF     = 64 * SBW;            // 16896 floats
constexpr int R_SMEMF = 3 * DEPF + WDF + 3 * 256;   // 43776 floats
constexpr int R_SMEMB = R_SMEMF * 4;         // 175104 bytes
constexpr int NCH     = 49;

__global__ void __launch_bounds__(256, 1) kernel_r(
    const float* __restrict__ depc, const float* __restrict__ Wda,
    float* __restrict__ rout) {

    extern __shared__ float sm[];
    float* dep_b0 = sm;
    float* wd_s   = sm + 3 * DEPF;
    float* a_b0   = wd_s + WDF;
    uint32_t s_dep[3], s_a[3];
    #pragma unroll
    for (int q = 0; q < 3; q++) {
        s_dep[q] = (uint32_t)__cvta_generic_to_shared(dep_b0 + q * DEPF);
        s_a[q]   = (uint32_t)__cvta_generic_to_shared(a_b0 + q * 256);
    }

    const int tid = threadIdx.x;
    const int nt  = blockIdx.x;   // 0..2 N-tile of 256 cols

    // cp.async issue of one bi's dep tile + A row into ring slot `buf`
    auto issue = [&](int bi_, int buf) {
        const float4* src = (const float4*)(depc + (size_t)bi_ * 8192);
        const uint32_t db = s_dep[buf];
        #pragma unroll
        for (int it = 0; it < 8; it++) {
            int idx = tid + it * 256;
            int j = idx >> 4, c4 = idx & 15;
            cpasync16(db + (uint32_t)(j * SD + c4 * 4) * 4, src + idx);
        }
        if (tid < 64)
            cpasync16(s_a[buf] + (uint32_t)tid * 16,
                      (const float4*)(g_A + (size_t)bi_ * 768 + nt * 256) + tid);
        cp_commit();
    };

    int bi = blockIdx.y;
    issue(bi, 0);                 // slot 0 in flight

    // ---- Wd_attn slice [64 x 256], column-permuted for STG.128 epilogue (once) ----
    // actual col A = 16q+4T+d -> logical L = 16q + 8*(d>>1) + 2T + (d&1)
    #pragma unroll
    for (int it = 0; it < 16; it++) {
        int idx = tid + it * 256;
        int k = idx >> 6, c4 = idx & 63;
        float4 v = *(const float4*)(Wda + (size_t)k * 768 + nt * 256 + c4 * 4);
        int A  = c4 * 4;
        int L0 = (A & ~15) + (((A >> 2) & 3) << 1);
        *(float2*)(wd_s + k * SBW + L0)     = make_float2(to_tf32(v.x), to_tf32(v.y));
        *(float2*)(wd_s + k * SBW + L0 + 8) = make_float2(to_tf32(v.z), to_tf32(v.w));
    }

    const int w  = tid >> 5, lane = tid & 31;
    const int g  = lane >> 2, t = lane & 3;
    const int wm = w >> 2, wn = w & 3;   // 2 x 4 warps

    int cur = 0;
    while (true) {
        const int bin = bi + NCH;
        if (bin < 1024) { issue(bin, cur == 2 ? 0 : cur + 1); cp_wait<1>(); }
        else            { cp_wait<0>(); }
        __syncthreads();   // slot `cur` (and wd_s on iter 0) visible to all warps

        const float* dep_s = dep_b0 + cur * DEPF;
        const float* a_s   = a_b0 + cur * 256;
        float* rbase = rout + (size_t)bi * 98304 + nt * 256;

        // two N-halves of 128 cols; warp tile 64 x 32 per half
        #pragma unroll
        for (int h = 0; h < 2; h++) {
            float acc[4][4][4];
            #pragma unroll
            for (int mf = 0; mf < 4; mf++)
                #pragma unroll
                for (int nf = 0; nf < 4; nf++)
                    #pragma unroll
                    for (int q = 0; q < 4; q++) acc[mf][nf][q] = 0.f;

            #pragma unroll
            for (int ks = 0; ks < 8; ks++) {
                const int kb = ks * 8;
                uint32_t a[4][4], b[4][2];
                #pragma unroll
                for (int mf = 0; mf < 4; mf++) {
                    int r = wm * 64 + mf * 16 + g;
                    a[mf][0] = __float_as_uint(dep_s[r * SD + kb + t]);
                    a[mf][1] = __float_as_uint(dep_s[(r + 8) * SD + kb + t]);
                    a[mf][2] = __float_as_uint(dep_s[r * SD + kb + 4 + t]);
                    a[mf][3] = __float_as_uint(dep_s[(r + 8) * SD + kb + 4 + t]);
                }
                #pragma unroll
                for (int nf = 0; nf < 4; nf++) {
                    int c = h * 128 + wn * 32 + nf * 8 + g;   // logical column
                    b[nf][0] = __float_as_uint(wd_s[(kb + t) * SBW + c]);
                    b[nf][1] = __float_as_uint(wd_s[(kb + 4 + t) * SBW + c]);
                }
                #pragma unroll
                for (int mf = 0; mf < 4; mf++)
                    #pragma unroll
                    for (int nf = 0; nf < 4; nf++) mma8(acc[mf][nf], a[mf], b[nf]);
            }

            // epilogue for this half: +A, STG.128 streaming (de-permuted columns);
            // fire-and-forget -> drains under the other half's / next iter's mma.
            #pragma unroll
            for (int mf = 0; mf < 4; mf++) {
                #pragma unroll
                for (int q2 = 0; q2 < 2; q2++) {
                    int r0  = wm * 64 + mf * 16 + g;
                    int col = h * 128 + wn * 32 + (q2 << 4) + 4 * t;
                    float4 a4 = *(const float4*)(a_s + col);
                    float4 w0 = make_float4(acc[mf][2 * q2][0] + a4.x, acc[mf][2 * q2][1] + a4.y,
                                            acc[mf][2 * q2 + 1][0] + a4.z, acc[mf][2 * q2 + 1][1] + a4.w);
                    float4 w1 = make_float4(acc[mf][2 * q2][2] + a4.x, acc[mf][2 * q2][3] + a4.y,
                                            acc[mf][2 * q2 + 1][2] + a4.z, acc[mf][2 * q2 + 1][3] + a4.w);
                    __stcs((float4*)(rbase + (size_t)r0 * 768 + col), w0);
                    __stcs((float4*)(rbase + (size_t)(r0 + 8) * 768 + col), w1);
                }
            }
        }

        bi = bin;
        if (bi >= 1024) break;
        cur = (cur == 2) ? 0 : cur + 1;
    }
}

// ---------------- launch ----------------
extern "C" void kernel_launch(void* const* d_in, const int* in_sizes, int n_in,
                              void* d_out, int out_size) {
    const float* text = (const float*)d_in[0];
    const int*   adj  = (const int*)d_in[1];
    const float* dep  = (const float*)d_in[2];
    const float* pos  = (const float*)d_in[3];
    const float* Wt   = (const float*)d_in[4];
    const float* Wpa  = (const float*)d_in[5];
    const float* Wda  = (const float*)d_in[6];
    const float* ba   = (const float*)d_in[7];
    const float* Wd   = (const float*)d_in[8];
    const float* bd   = (const float*)d_in[9];
    const float* Wp   = (const float*)d_in[10];
    const float* bp   = (const float*)d_in[11];
    float* out = (float*)d_out;

    cudaFuncSetAttribute(kernel_r, cudaFuncAttributeMaxDynamicSharedMemorySize, R_SMEMB);

    float* depc_ptr;
    cudaGetSymbolAddress((void**)&depc_ptr, g_depc);

    // 1) row sums + combined bias
    k0_sums<<<116, 256>>>(Wt, Wpa, Wda, ba, bd, bp);
    // 2) A = text@Wt + pos@Wp_attn + b_attn  -> g_A
    gemm_small<<<dim3(6, 16), 128>>>(text, 768, Wt, 768, pos, 64, Wpa, 64,
                                     /*use_pd=*/0, ba, nullptr, nullptr);
    // 3) scores/softmax -> p (out), g_pd, and tf32-rounded dep copy -> g_depc
    kernel_s<<<BI, 128>>>(text, adj, dep, pos, out + P_OFF);
    // 4) r = dep@Wd_attn + A  -> out[0 : R_SIZE)   (persistent, split-N pipelined)
    kernel_r<<<dim3(3, NCH), 256, R_SMEMB>>>(depc_ptr, Wda, out);
    // 5) output_sum = pos@Wp + g_pd@Wd + (bp+bd) + text -> out[OS_OFF : )
    gemm_small<<<dim3(6, 16), 128>>>(pos, 64, Wp, 64, nullptr, 64, Wd, 64,
                                     /*use_pd=*/1, nullptr, text, out + OS_OFF);
}

// round 11
// speedup vs baseline: 1.5301x; 1.1845x over previous
#include <cuda_runtime.h>
#include <cstdint>
#include <cstddef>

// ---------------- problem constants ----------------
constexpr int Bb   = 8;
constexpr int Ll   = 128;
constexpr int Dd   = 768;
constexpr int DEP  = 64;
constexpr int POSN = 64;
constexpr int OUTN = 768;
constexpr int BI   = Bb * Ll;                       // 1024 (b,i) rows
constexpr long long R_SIZE = (long long)BI * Ll * OUTN;   // 100663296
constexpr long long OS_OFF = R_SIZE;                       // output_sum offset
constexpr long long P_OFF  = R_SIZE + (long long)BI * OUTN; // p offset
#define NEGC (-1e30f)

// ---------------- scratch (device globals; no allocs) ----------------
__device__ __align__(16) float g_A[BI * OUTN];     // A[b,i,o]
__device__ __align__(16) float g_pd[BI * DEP];     // sum_j p * dep
__device__ float g_wt_sum[Dd];
__device__ float g_wp_sum[POSN];
__device__ float g_wd_sum[DEP];
__device__ float g_bias_out[OUTN];                 // bp + bd
__device__ float g_bsum;                           // sum(b_attn)

// ---------------- helpers ----------------
__device__ __forceinline__ float to_tf32(float x) {
    uint32_t u;
    asm("cvt.rna.tf32.f32 %0, %1;" : "=r"(u) : "f"(x));
    return __uint_as_float(u);
}
__device__ __forceinline__ void mma8(float c[4], const uint32_t a[4], const uint32_t b[2]) {
    asm volatile(
        "mma.sync.aligned.m16n8k8.row.col.f32.tf32.tf32.f32 "
        "{%0,%1,%2,%3},{%4,%5,%6,%7},{%8,%9},{%0,%1,%2,%3};\n"
        : "+f"(c[0]), "+f"(c[1]), "+f"(c[2]), "+f"(c[3])
        : "r"(a[0]), "r"(a[1]), "r"(a[2]), "r"(a[3]), "r"(b[0]), "r"(b[1]));
}

// ---------------- K0: row sums + combined bias (warp-per-row) ----------------
__global__ void k0_sums(const float* __restrict__ Wt, const float* __restrict__ Wpa,
                        const float* __restrict__ Wda, const float* __restrict__ b_attn,
                        const float* __restrict__ bd, const float* __restrict__ bp) {
    const int gw   = (blockIdx.x * blockDim.x + threadIdx.x) >> 5;
    const int lane = threadIdx.x & 31;
    if (gw <= 896) {
        const float* src;
        if (gw < 768)      src = Wt  + (size_t)gw * 768;
        else if (gw < 832) src = Wpa + (size_t)(gw - 768) * 768;
        else if (gw < 896) src = Wda + (size_t)(gw - 832) * 768;
        else               src = b_attn;
        const float4* p4 = (const float4*)src;
        float s = 0.f;
        #pragma unroll
        for (int i = 0; i < 6; i++) { float4 v = p4[lane + i * 32]; s += v.x + v.y + v.z + v.w; }
        #pragma unroll
        for (int o = 16; o; o >>= 1) s += __shfl_xor_sync(0xffffffffu, s, o);
        if (lane == 0) {
            if (gw < 768)      g_wt_sum[gw] = s;
            else if (gw < 832) g_wp_sum[gw - 768] = s;
            else if (gw < 896) g_wd_sum[gw - 832] = s;
            else               g_bsum = s;
        }
    } else if (gw >= 897 && gw < 921) {
        int n = (gw - 897) * 32 + lane;
        g_bias_out[n] = bp[n] + bd[n];
    }
}

// ---------------- gemm_small (R6 version): BM=64, BN=128, BK=32, 4 warps ----------------
__global__ void __launch_bounds__(128) gemm_small(
    const float* __restrict__ A1, int lda1, const float* __restrict__ B1, int K1,
    const float* __restrict__ A2_, int lda2, const float* __restrict__ B2, int K2,
    int use_pd, const float* __restrict__ bias_, const float* __restrict__ addend,
    float* __restrict__ out_) {

    __shared__ float a_sm[64 * 36];
    __shared__ float b_sm[32 * 136];
    __shared__ float bias_s[128];

    const int tid   = threadIdx.x;
    const int nbase = blockIdx.x * 128;
    const int mbase = blockIdx.y * 64;
    const float* A2   = use_pd ? g_pd : A2_;
    float*       out  = out_ ? out_ : g_A;
    const float* bias = bias_ ? bias_ : g_bias_out;

    bias_s[tid] = bias[nbase + tid];

    const int w  = tid >> 5, lane = tid & 31;
    const int g  = lane >> 2, t = lane & 3;
    const int wm = w >> 1, wn = w & 1;

    float acc[2][8][4];
    #pragma unroll
    for (int mf = 0; mf < 2; mf++)
        #pragma unroll
        for (int nf = 0; nf < 8; nf++)
            #pragma unroll
            for (int q = 0; q < 4; q++) acc[mf][nf][q] = 0.f;

    #pragma unroll
    for (int s = 0; s < 2; s++) {
        const float* Ap = s ? A2 : A1;
        const float* Bp = s ? B2 : B1;
        const int lda   = s ? lda2 : lda1;
        const int Ks    = s ? K2 : K1;
        for (int kt = 0; kt < Ks; kt += 32) {
            #pragma unroll
            for (int it = 0; it < 4; it++) {
                int idx = tid + it * 128;
                int row = idx >> 3, k4 = idx & 7;
                float4 v = *(const float4*)(Ap + (size_t)(mbase + row) * lda + kt + k4 * 4);
                float4 wv = make_float4(to_tf32(v.x), to_tf32(v.y), to_tf32(v.z), to_tf32(v.w));
                *(float4*)(a_sm + row * 36 + k4 * 4) = wv;
            }
            #pragma unroll
            for (int it = 0; it < 8; it++) {
                int idx = tid + it * 128;
                int kr = idx >> 5, c4 = idx & 31;
                float4 v = *(const float4*)(Bp + (size_t)(kt + kr) * 768 + nbase + c4 * 4);
                float4 wv = make_float4(to_tf32(v.x), to_tf32(v.y), to_tf32(v.z), to_tf32(v.w));
                *(float4*)(b_sm + kr * 136 + c4 * 4) = wv;
            }
            __syncthreads();
            #pragma unroll
            for (int ks = 0; ks < 4; ks++) {
                const int kb = ks * 8;
                uint32_t a[2][4], b[8][2];
                #pragma unroll
                for (int mf = 0; mf < 2; mf++) {
                    int r = wm * 32 + mf * 16 + g;
                    a[mf][0] = __float_as_uint(a_sm[r * 36 + kb + t]);
                    a[mf][1] = __float_as_uint(a_sm[(r + 8) * 36 + kb + t]);
                    a[mf][2] = __float_as_uint(a_sm[r * 36 + kb + 4 + t]);
                    a[mf][3] = __float_as_uint(a_sm[(r + 8) * 36 + kb + 4 + t]);
                }
                #pragma unroll
                for (int nf = 0; nf < 8; nf++) {
                    int c = wn * 64 + nf * 8 + g;
                    b[nf][0] = __float_as_uint(b_sm[(kb + t) * 136 + c]);
                    b[nf][1] = __float_as_uint(b_sm[(kb + 4 + t) * 136 + c]);
                }
                #pragma unroll
                for (int mf = 0; mf < 2; mf++)
                    #pragma unroll
                    for (int nf = 0; nf < 8; nf++) mma8(acc[mf][nf], a[mf], b[nf]);
            }
            __syncthreads();
        }
    }

    #pragma unroll
    for (int mf = 0; mf < 2; mf++) {
        #pragma unroll
        for (int nf = 0; nf < 8; nf++) {
            int r0 = mbase + wm * 32 + mf * 16 + g;
            int cl = wn * 64 + nf * 8 + 2 * t;
            int c  = nbase + cl;
            float a0 = 0.f, a1 = 0.f, a2 = 0.f, a3 = 0.f;
            if (addend) {
                a0 = addend[(size_t)r0 * 768 + c];
                a1 = addend[(size_t)r0 * 768 + c + 1];
                a2 = addend[(size_t)(r0 + 8) * 768 + c];
                a3 = addend[(size_t)(r0 + 8) * 768 + c + 1];
            }
            float2 v0 = make_float2(acc[mf][nf][0] + bias_s[cl] + a0,
                                    acc[mf][nf][1] + bias_s[cl + 1] + a1);
            float2 v1 = make_float2(acc[mf][nf][2] + bias_s[cl] + a2,
                                    acc[mf][nf][3] + bias_s[cl + 1] + a3);
            *(float2*)(out + (size_t)r0 * 768 + c) = v0;
            *(float2*)(out + (size_t)(r0 + 8) * 768 + c) = v1;
        }
    }
}

// ---------------- kernel S (R6 version): scores + softmax + p + p-weighted dep ----------------
__global__ void __launch_bounds__(128) kernel_s(
    const float* __restrict__ text, const int* __restrict__ adj,
    const float* __restrict__ dep, const float* __restrict__ pos,
    float* __restrict__ p_out) {

    __shared__ float dep_s[128 * 65];
    __shared__ float ws_s[64];
    __shared__ float p_s[128];
    __shared__ float red[128];

    const int bi  = blockIdx.x;
    const int tid = threadIdx.x;
    const int lane = tid & 31;

    if (tid < 64) ws_s[tid] = g_wd_sum[tid];

    float ps = 0.f;
    #pragma unroll
    for (int d = tid; d < 768; d += 128) ps += text[(size_t)bi * 768 + d] * g_wt_sum[d];
    if (tid < 64) ps += pos[(size_t)bi * 64 + tid] * g_wp_sum[tid];
    #pragma unroll
    for (int o = 16; o; o >>= 1) ps += __shfl_xor_sync(0xffffffffu, ps, o);
    if (lane == 0) red[tid >> 5] = ps;
    __syncthreads();
    const float s_base = red[0] + red[1] + red[2] + red[3] + g_bsum;
    __syncthreads();

    const float4* dr = (const float4*)(dep + ((size_t)bi * 128 + tid) * 64);
    float dot = 0.f;
    #pragma unroll
    for (int q = 0; q < 16; q++) {
        float4 v = dr[q];
        dot += v.x * ws_s[4 * q] + v.y * ws_s[4 * q + 1] + v.z * ws_s[4 * q + 2] + v.w * ws_s[4 * q + 3];
        int base = tid * 65 + 4 * q;
        dep_s[base]     = v.x;
        dep_s[base + 1] = v.y;
        dep_s[base + 2] = v.z;
        dep_s[base + 3] = v.w;
    }
    const float score = s_base + dot + (adj[(size_t)bi * 128 + tid] == 0 ? NEGC : 0.f);

    float m = score;
    #pragma unroll
    for (int o = 16; o; o >>= 1) m = fmaxf(m, __shfl_xor_sync(0xffffffffu, m, o));
    if (lane == 0) red[tid >> 5] = m;
    __syncthreads();
    const float mx = fmaxf(fmaxf(red[0], red[1]), fmaxf(red[2], red[3]));
    __syncthreads();
    const float e = expf(score - mx);
    float z = e;
    #pragma unroll
    for (int o = 16; o; o >>= 1) z += __shfl_xor_sync(0xffffffffu, z, o);
    if (lane == 0) red[tid >> 5] = z;
    __syncthreads();
    const float Z = red[0] + red[1] + red[2] + red[3];
    const float p = e / Z;
    p_s[tid] = p;
    p_out[(size_t)bi * 128 + tid] = p;
    __syncthreads();

    const int half = tid >> 6, k = tid & 63;
    float s = 0.f;
    #pragma unroll 4
    for (int j = half * 64; j < half * 64 + 64; j++) s += p_s[j] * dep_s[j * 65 + k];
    red[tid] = s;
    __syncthreads();
    if (tid < 64) g_pd[(size_t)bi * 64 + tid] = red[tid] + red[tid + 64];
}

// ---------------- kernel R: r = dep @ Wd_attn + A  (persistent; R6 loads + split-N stores) ----------------
// grid (3, 49) = 147 CTAs (one wave). 256 thr = 8 warps (2 wm x 4 wn).
// dep tile prefetched into registers (LDG) one bi ahead, cvt+STS at iteration start.
// N-tile 256 processed as two 128-col halves so each half's STG.128 burst drains
// under the next half's / next iteration's mma.
constexpr int SD      = 68;                  // dep_s row stride (mod32==4)
constexpr int SBW     = 264;                 // wd_s row stride (mod32==8)
constexpr int R_DEPS  = 128 * SD;            // 8704 floats
constexpr int WDF     = 64 * SBW;            // 16896 floats
constexpr int R_SMEMB = (R_DEPS + WDF + 256) * 4;   // 103424 bytes
constexpr int NCH     = 49;

__global__ void __launch_bounds__(256, 1) kernel_r(
    const float* __restrict__ dep, const float* __restrict__ Wda,
    float* __restrict__ rout) {

    extern __shared__ float sm[];
    float* dep_s = sm;
    float* wd_s  = sm + R_DEPS;
    float* a_s   = wd_s + WDF;

    const int tid = threadIdx.x;
    const int nt  = blockIdx.x;   // 0..2 N-tile of 256 cols

    // ---- Wd_attn slice [64 x 256], column-permuted for STG.128 epilogue (once) ----
    // actual col A = 16q+4T+d -> logical L = 16q + 8*(d>>1) + 2T + (d&1)
    #pragma unroll
    for (int it = 0; it < 16; it++) {
        int idx = tid + it * 256;
        int k = idx >> 6, c4 = idx & 63;
        float4 v = *(const float4*)(Wda + (size_t)k * 768 + nt * 256 + c4 * 4);
        int A  = c4 * 4;
        int L0 = (A & ~15) + (((A >> 2) & 3) << 1);
        *(float2*)(wd_s + k * SBW + L0)     = make_float2(to_tf32(v.x), to_tf32(v.y));
        *(float2*)(wd_s + k * SBW + L0 + 8) = make_float2(to_tf32(v.z), to_tf32(v.w));
    }

    const int w  = tid >> 5, lane = tid & 31;
    const int g  = lane >> 2, t = lane & 3;
    const int wm = w >> 2, wn = w & 3;   // 2 x 4 warps

    int bi = blockIdx.y;                 // strided by NCH

    // prefetch first dep tile + A row into registers
    float4 pf[8];
    float  pfa;
    {
        const float4* db4 = (const float4*)(dep + (size_t)bi * 8192);
        #pragma unroll
        for (int it = 0; it < 8; it++) pf[it] = db4[tid + it * 256];
        pfa = g_A[(size_t)bi * 768 + nt * 256 + tid];
    }

    while (true) {
        __syncthreads();   // prior iteration's consumers done (iter0: wd_s init done)
        #pragma unroll
        for (int it = 0; it < 8; it++) {
            int idx = tid + it * 256;
            int j = idx >> 4, k4 = idx & 15;
            float4 v = pf[it];
            *(float4*)(dep_s + j * SD + k4 * 4) =
                make_float4(to_tf32(v.x), to_tf32(v.y), to_tf32(v.z), to_tf32(v.w));
        }
        a_s[tid] = pfa;
        __syncthreads();

        // prefetch next bi (hidden under mma + stores)
        const int bin = bi + NCH;
        if (bin < 1024) {
            const float4* db4 = (const float4*)(dep + (size_t)bin * 8192);
            #pragma unroll
            for (int it = 0; it < 8; it++) pf[it] = db4[tid + it * 256];
            pfa = g_A[(size_t)bin * 768 + nt * 256 + tid];
        }

        float* rbase = rout + (size_t)bi * 98304 + nt * 256;

        // two N-halves of 128 cols; warp tile 64 x 32 per half
        #pragma unroll
        for (int h = 0; h < 2; h++) {
            float acc[4][4][4];
            #pragma unroll
            for (int mf = 0; mf < 4; mf++)
                #pragma unroll
                for (int nf = 0; nf < 4; nf++)
                    #pragma unroll
                    for (int q = 0; q < 4; q++) acc[mf][nf][q] = 0.f;

            #pragma unroll
            for (int ks = 0; ks < 8; ks++) {
                const int kb = ks * 8;
                uint32_t a[4][4], b[4][2];
                #pragma unroll
                for (int mf = 0; mf < 4; mf++) {
                    int r = wm * 64 + mf * 16 + g;
                    a[mf][0] = __float_as_uint(dep_s[r * SD + kb + t]);
                    a[mf][1] = __float_as_uint(dep_s[(r + 8) * SD + kb + t]);
                    a[mf][2] = __float_as_uint(dep_s[r * SD + kb + 4 + t]);
                    a[mf][3] = __float_as_uint(dep_s[(r + 8) * SD + kb + 4 + t]);
                }
                #pragma unroll
                for (int nf = 0; nf < 4; nf++) {
                    int c = h * 128 + wn * 32 + nf * 8 + g;   // logical column
                    b[nf][0] = __float_as_uint(wd_s[(kb + t) * SBW + c]);
                    b[nf][1] = __float_as_uint(wd_s[(kb + 4 + t) * SBW + c]);
                }
                #pragma unroll
                for (int mf = 0; mf < 4; mf++)
                    #pragma unroll
                    for (int nf = 0; nf < 4; nf++) mma8(acc[mf][nf], a[mf], b[nf]);
            }

            // epilogue for this half: +A, STG.128 streaming (de-permuted columns)
            #pragma unroll
            for (int mf = 0; mf < 4; mf++) {
                #pragma unroll
                for (int q2 = 0; q2 < 2; q2++) {
                    int r0  = wm * 64 + mf * 16 + g;
                    int col = h * 128 + wn * 32 + (q2 << 4) + 4 * t;
                    float4 a4 = *(const float4*)(a_s + col);
                    float4 w0 = make_float4(acc[mf][2 * q2][0] + a4.x, acc[mf][2 * q2][1] + a4.y,
                                            acc[mf][2 * q2 + 1][0] + a4.z, acc[mf][2 * q2 + 1][1] + a4.w);
                    float4 w1 = make_float4(acc[mf][2 * q2][2] + a4.x, acc[mf][2 * q2][3] + a4.y,
                                            acc[mf][2 * q2 + 1][2] + a4.z, acc[mf][2 * q2 + 1][3] + a4.w);
                    __stcs((float4*)(rbase + (size_t)r0 * 768 + col), w0);
                    __stcs((float4*)(rbase + (size_t)(r0 + 8) * 768 + col), w1);
                }
            }
        }

        bi = bin;
        if (bi >= 1024) break;
    }
}

// ---------------- launch (fork/join two-stream pipeline) ----------------
extern "C" void kernel_launch(void* const* d_in, const int* in_sizes, int n_in,
                              void* d_out, int out_size) {
    const float* text = (const float*)d_in[0];
    const int*   adj  = (const int*)d_in[1];
    const float* dep  = (const float*)d_in[2];
    const float* pos  = (const float*)d_in[3];
    const float* Wt   = (const float*)d_in[4];
    const float* Wpa  = (const float*)d_in[5];
    const float* Wda  = (const float*)d_in[6];
    const float* ba   = (const float*)d_in[7];
    const float* Wd   = (const float*)d_in[8];
    const float* bd   = (const float*)d_in[9];
    const float* Wp   = (const float*)d_in[10];
    const float* bp   = (const float*)d_in[11];
    float* out = (float*)d_out;

    // one-time resources (host-side only; no device memory)
    static cudaStream_t sB = nullptr;
    static cudaEvent_t  eF = nullptr, eJ = nullptr;
    if (sB == nullptr) {
        cudaStreamCreateWithFlags(&sB, cudaStreamNonBlocking);
        cudaEventCreateWithFlags(&eF, cudaEventDisableTiming);
        cudaEventCreateWithFlags(&eJ, cudaEventDisableTiming);
        cudaFuncSetAttribute(kernel_r, cudaFuncAttributeMaxDynamicSharedMemorySize, R_SMEMB);
    }

    // fork: side chain {k0 -> kernel_s -> gemm2} on sB
    cudaEventRecord(eF, 0);
    cudaStreamWaitEvent(sB, eF, 0);

    k0_sums<<<116, 256, 0, sB>>>(Wt, Wpa, Wda, ba, bd, bp);
    kernel_s<<<BI, 128, 0, sB>>>(text, adj, dep, pos, out + P_OFF);
    // output_sum = pos@Wp + g_pd@Wd + (bp+bd) + text -> out[OS_OFF : )
    gemm_small<<<dim3(6, 16), 128, 0, sB>>>(pos, 64, Wp, 64, nullptr, 64, Wd, 64,
                                            /*use_pd=*/1, nullptr, text, out + OS_OFF);
    cudaEventRecord(eJ, sB);

    // main chain: gemm1 -> kernel_r (overlaps with the side chain)
    gemm_small<<<dim3(6, 16), 128>>>(text, 768, Wt, 768, pos, 64, Wpa, 64,
                                     /*use_pd=*/0, ba, nullptr, nullptr);
    kernel_r<<<dim3(3, NCH), 256, R_SMEMB>>>(dep, Wda, out);

    // join side chain back into the capture-origin stream
    cudaStreamWaitEvent(0, eJ, 0);
}